// round 1
// baseline (speedup 1.0000x reference)
#include <cuda_runtime.h>
#include <cuda_bf16.h>
#include <cstdint>

// ---------------- problem constants ----------------
#define Bsz 8
#define Tsz 1024
#define Msz (Bsz*Tsz)        // 8192
#define DM  256
#define DI  512
#define DS  16
#define DTR 16
#define NCLS 60
#define KF  232              // 225 padded to mult of 8

// ---------------- device scratch ----------------
__device__ float g_featK[Msz*KF];
__device__ float g_embed_wp[DM*KF];
__device__ float g_feat[Msz*DM];
__device__ float g_hn[Msz*DM];
__device__ float g_xz[(size_t)Msz*1024];
__device__ float g_xmc[Msz*DI];
__device__ float g_dbl[Msz*48];
__device__ float g_delta[Msz*DI];
__device__ float g_y[Msz*DI];
__device__ float g_pooled[Bsz*DM];

__device__ __forceinline__ float softplusf(float v){
    return v > 20.f ? v : log1pf(expf(v));
}
__device__ __forceinline__ float siluf(float v){
    return v / (1.f + __expf(-v));
}

// ---------------- feature construction ----------------
// pos = x - x[:,:,0:1,:]; vel = diff_t(pos) (0 at t=0); acc = diff_t(vel)
__global__ void feat_kernel(const float* __restrict__ x){
    int i = blockIdx.x*blockDim.x + threadIdx.x;
    if (i >= Msz*25) return;
    int j = i % 25;
    int m = i / 25;
    int t = m & (Tsz-1);
    const float* xr  = x + (size_t)m*75;
    const float* xr1 = xr - 75;
    const float* xr2 = xr - 150;
    float* o = g_featK + (size_t)m*KF + j*9;
    #pragma unroll
    for (int c = 0; c < 3; c++){
        float p0 = xr[j*3+c]  - xr[c];
        float p1 = (t>=1) ? (xr1[j*3+c] - xr1[c]) : 0.f;
        float p2 = (t>=2) ? (xr2[j*3+c] - xr2[c]) : 0.f;
        float vel   = (t>=1) ? (p0 - p1) : 0.f;
        float velm1 = (t>=2) ? (p1 - p2) : 0.f;
        float acc   = (t>=1) ? (vel - velm1) : 0.f;
        o[c]   = p0;
        o[3+c] = vel;
        o[6+c] = acc;
    }
    if (j == 0){
        #pragma unroll
        for (int k = 225; k < KF; k++) g_featK[(size_t)m*KF + k] = 0.f;
    }
}

__global__ void padw_kernel(const float* __restrict__ ew){
    int i = blockIdx.x*blockDim.x + threadIdx.x;
    if (i >= DM*KF) return;
    int n = i / KF, k = i % KF;
    g_embed_wp[i] = (k < 225) ? ew[n*225 + k] : 0.f;
}

// ---------------- generic SGEMM (NT): C[M,N] = A[M,K] @ W[N,K]^T ----------------
// Requirements: M % 128 == 0, K % 8 == 0, lda/ldw mult of 4, 16B-aligned rows.
// Epilogue: +bias (opt), softplus if act==1, +addC (opt).
__global__ __launch_bounds__(256) void sgemm_nt(
    int M, int N, int K,
    const float* __restrict__ A, int lda,
    const float* __restrict__ W, int ldw,
    float* __restrict__ C, int ldc,
    const float* __restrict__ bias,
    const float* __restrict__ addC, int ldadd,
    int act)
{
    __shared__ float As[8][132];
    __shared__ float Ws[8][132];
    const int bm = blockIdx.y * 128;
    const int bn = blockIdx.x * 128;
    const int tid = threadIdx.x;
    const int lr = tid >> 1;          // load row in tile (0..127)
    const int lc = (tid & 1) * 4;     // load col offset (0 or 4)
    const int tr = (tid >> 4) << 3;   // compute row offset
    const int tc = (tid & 15) << 3;   // compute col offset

    float acc[8][8];
    #pragma unroll
    for (int i = 0; i < 8; i++)
        #pragma unroll
        for (int j = 0; j < 8; j++) acc[i][j] = 0.f;

    const float* Aptr = A + (size_t)(bm + lr) * lda + lc;
    const bool wvalid = (bn + lr) < N;
    const float* Wptr = W + (size_t)(bn + lr) * ldw + lc;

    for (int k0 = 0; k0 < K; k0 += 8){
        float4 av = *(const float4*)(Aptr + k0);
        float4 wv = wvalid ? *(const float4*)(Wptr + k0) : make_float4(0.f,0.f,0.f,0.f);
        As[lc+0][lr] = av.x; As[lc+1][lr] = av.y; As[lc+2][lr] = av.z; As[lc+3][lr] = av.w;
        Ws[lc+0][lr] = wv.x; Ws[lc+1][lr] = wv.y; Ws[lc+2][lr] = wv.z; Ws[lc+3][lr] = wv.w;
        __syncthreads();
        #pragma unroll
        for (int kk = 0; kk < 8; kk++){
            float ra[8], rb[8];
            *(float4*)(ra)   = *(const float4*)&As[kk][tr];
            *(float4*)(ra+4) = *(const float4*)&As[kk][tr+4];
            *(float4*)(rb)   = *(const float4*)&Ws[kk][tc];
            *(float4*)(rb+4) = *(const float4*)&Ws[kk][tc+4];
            #pragma unroll
            for (int i = 0; i < 8; i++)
                #pragma unroll
                for (int j = 0; j < 8; j++)
                    acc[i][j] = fmaf(ra[i], rb[j], acc[i][j]);
        }
        __syncthreads();
    }

    #pragma unroll
    for (int i = 0; i < 8; i++){
        int m = bm + tr + i;
        float* crow = C + (size_t)m * ldc;
        const float* arow = addC ? addC + (size_t)m * ldadd : nullptr;
        #pragma unroll
        for (int j = 0; j < 8; j++){
            int nn = bn + tc + j;
            if (nn < N){
                float v = acc[i][j];
                if (bias) v += bias[nn];
                if (act)  v  = softplusf(v);
                if (arow) v += arow[nn];
                crow[nn] = v;
            }
        }
    }
}

// ---------------- layernorm over last dim = 256 ----------------
__global__ __launch_bounds__(256) void ln_kernel(
    const float* __restrict__ in, const float* __restrict__ g,
    const float* __restrict__ bta, float* __restrict__ out)
{
    int m = blockIdx.x;
    int c = threadIdx.x;
    float v = in[(size_t)m*DM + c];
    float s = v, q = v*v;
    #pragma unroll
    for (int o = 16; o; o >>= 1){
        s += __shfl_xor_sync(0xffffffffu, s, o);
        q += __shfl_xor_sync(0xffffffffu, q, o);
    }
    __shared__ float red[2][8];
    int w = c >> 5, l = c & 31;
    if (l == 0){ red[0][w] = s; red[1][w] = q; }
    __syncthreads();
    float S = 0.f, Q = 0.f;
    #pragma unroll
    for (int i = 0; i < 8; i++){ S += red[0][i]; Q += red[1][i]; }
    float mu  = S * (1.f/256.f);
    float var = Q * (1.f/256.f) - mu*mu;
    float inv = rsqrtf(var + 1e-5f);
    out[(size_t)m*DM + c] = (v - mu) * inv * g[c] + bta[c];
}

// ---------------- causal depthwise conv (k=4) + silu ----------------
__global__ void conv_silu_kernel(const float* __restrict__ cw, const float* __restrict__ cb){
    int i = blockIdx.x*blockDim.x + threadIdx.x;   // over Msz*DI
    int d = i & (DI-1);
    int m = i >> 9;
    int t = m & (Tsz-1);
    float w0 = cw[d*4+0], w1 = cw[d*4+1], w2 = cw[d*4+2], w3 = cw[d*4+3];
    float a = cb[d];
    a = fmaf(w3, g_xz[(size_t)m*1024 + d], a);
    if (t >= 1) a = fmaf(w2, g_xz[(size_t)(m-1)*1024 + d], a);
    if (t >= 2) a = fmaf(w1, g_xz[(size_t)(m-2)*1024 + d], a);
    if (t >= 3) a = fmaf(w0, g_xz[(size_t)(m-3)*1024 + d], a);
    g_xmc[i] = siluf(a);
}

// ---------------- selective scan ----------------
// lane layout: warp handles 2 channels d (16 lanes each, n = lane&15)
__global__ __launch_bounds__(256) void scan_kernel(
    const float* __restrict__ A_log, const float* __restrict__ Dp)
{
    int lane = threadIdx.x & 31;
    int warp = threadIdx.x >> 5;
    int b = blockIdx.x >> 5;                 // 32 blocks per batch
    int dbase = (blockIdx.x & 31) * 16;
    int d = dbase + warp*2 + (lane >> 4);
    int n = lane & 15;
    float a  = -expf(A_log[d*DS + n]);
    float Dd = Dp[d];
    float h = 0.f;
    size_t base = (size_t)b * Tsz;
    for (int t = 0; t < Tsz; t++){
        size_t row = base + t;
        float dv = g_delta[row*DI + d];
        float uv = g_xmc[row*DI + d];
        // one coalesced load covers B (lanes 0-15) and C (lanes 16-31)
        float bc = g_dbl[row*48 + 16 + lane];
        float Bn = __shfl_sync(0xffffffffu, bc, n);
        float Cn = __shfl_sync(0xffffffffu, bc, 16 + n);
        float dA = __expf(dv * a);
        h = fmaf(dA, h, dv * Bn * uv);
        float p = h * Cn;
        p += __shfl_xor_sync(0xffffffffu, p, 1);
        p += __shfl_xor_sync(0xffffffffu, p, 2);
        p += __shfl_xor_sync(0xffffffffu, p, 4);
        p += __shfl_xor_sync(0xffffffffu, p, 8);
        if (n == 0) g_y[row*DI + d] = fmaf(uv, Dd, p);
    }
}

// ---------------- gating: y *= silu(res) ----------------
__global__ void gate_kernel(){
    int i = blockIdx.x*blockDim.x + threadIdx.x;   // over Msz*DI
    int d = i & (DI-1);
    int m = i >> 9;
    float r = g_xz[(size_t)m*1024 + 512 + d];
    g_y[i] *= siluf(r);
}

// ---------------- mean pool over T ----------------
__global__ void pool_kernel(){
    int b = blockIdx.x;
    int c = threadIdx.x;
    const float* p = g_hn + (size_t)b*Tsz*DM + c;
    float s0=0.f, s1=0.f, s2=0.f, s3=0.f;
    for (int t = 0; t < Tsz; t += 4){
        s0 += p[(size_t)(t+0)*DM];
        s1 += p[(size_t)(t+1)*DM];
        s2 += p[(size_t)(t+2)*DM];
        s3 += p[(size_t)(t+3)*DM];
    }
    g_pooled[b*DM + c] = (s0+s1+s2+s3) * (1.f/1024.f);
}

// ---------------- classifier head ----------------
__global__ void fine_kernel(const float* __restrict__ fw, const float* __restrict__ fb,
                            float* __restrict__ out){
    int b = blockIdx.x;
    int nn = threadIdx.x;
    if (nn >= NCLS) return;
    const float* pr = g_pooled + b*DM;
    const float* wr = fw + nn*DM;
    float s = fb[nn];
    for (int k = 0; k < DM; k++) s = fmaf(pr[k], wr[k], s);
    out[b*NCLS + nn] = s;
}

// ---------------- launch ----------------
static float* sym_addr(const void* p){ return (float*)p; }

extern "C" void kernel_launch(void* const* d_in, const int* in_sizes, int n_in,
                              void* d_out, int out_size)
{
    const float* x          = (const float*)d_in[0];
    const float* embed_w    = (const float*)d_in[1];
    const float* embed_b    = (const float*)d_in[2];
    const float* pre_g      = (const float*)d_in[3];
    const float* pre_b      = (const float*)d_in[4];
    const float* in_proj_w  = (const float*)d_in[5];
    const float* conv_w     = (const float*)d_in[6];
    const float* conv_b     = (const float*)d_in[7];
    const float* x_proj_w   = (const float*)d_in[8];
    const float* dt_proj_w  = (const float*)d_in[9];
    const float* dt_proj_b  = (const float*)d_in[10];
    const float* A_log      = (const float*)d_in[11];
    const float* Dp         = (const float*)d_in[12];
    const float* out_proj_w = (const float*)d_in[13];
    const float* post_g     = (const float*)d_in[14];
    const float* post_b     = (const float*)d_in[15];
    const float* fine_w     = (const float*)d_in[16];
    const float* fine_b     = (const float*)d_in[17];
    float* out = (float*)d_out;

    void *p_featK, *p_ewp, *p_feat, *p_hn, *p_xz, *p_xmc, *p_dbl, *p_delta, *p_y;
    cudaGetSymbolAddress(&p_featK, g_featK);
    cudaGetSymbolAddress(&p_ewp,   g_embed_wp);
    cudaGetSymbolAddress(&p_feat,  g_feat);
    cudaGetSymbolAddress(&p_hn,    g_hn);
    cudaGetSymbolAddress(&p_xz,    g_xz);
    cudaGetSymbolAddress(&p_xmc,   g_xmc);
    cudaGetSymbolAddress(&p_dbl,   g_dbl);
    cudaGetSymbolAddress(&p_delta, g_delta);
    cudaGetSymbolAddress(&p_y,     g_y);

    // 1) features + padded weights
    padw_kernel<<<(DM*KF + 255)/256, 256>>>(embed_w);
    feat_kernel<<<(Msz*25 + 255)/256, 256>>>(x);

    // 2) embed GEMM: feat = featK @ embed_wp^T + embed_b
    sgemm_nt<<<dim3(2, Msz/128), 256>>>(Msz, DM, KF,
        (const float*)p_featK, KF, (const float*)p_ewp, KF,
        (float*)p_feat, DM, embed_b, nullptr, 0, 0);

    // 3) pre-LN
    ln_kernel<<<Msz, 256>>>((const float*)p_feat, pre_g, pre_b, (float*)p_hn);

    // 4) in_proj GEMM: xz = hn @ in_proj_w^T
    sgemm_nt<<<dim3(8, Msz/128), 256>>>(Msz, 1024, DM,
        (const float*)p_hn, DM, in_proj_w, DM,
        (float*)p_xz, 1024, nullptr, nullptr, 0, 0);

    // 5) depthwise conv + silu
    conv_silu_kernel<<<(Msz*DI)/256, 256>>>(conv_w, conv_b);

    // 6) x_proj GEMM: dbl = xmc @ x_proj_w^T
    sgemm_nt<<<dim3(1, Msz/128), 256>>>(Msz, 48, DI,
        (const float*)p_xmc, DI, x_proj_w, DI,
        (float*)p_dbl, 48, nullptr, nullptr, 0, 0);

    // 7) dt_proj GEMM + softplus: delta = softplus(dt @ dt_proj_w^T + b)
    sgemm_nt<<<dim3(4, Msz/128), 256>>>(Msz, DI, DTR,
        (const float*)p_dbl, 48, dt_proj_w, DTR,
        (float*)p_delta, DI, dt_proj_b, nullptr, 0, 1);

    // 8) selective scan
    scan_kernel<<<Bsz*32, 256>>>(A_log, Dp);

    // 9) gate
    gate_kernel<<<(Msz*DI)/256, 256>>>();

    // 10) out_proj GEMM + residual: feat = feat + y @ out_proj_w^T
    sgemm_nt<<<dim3(2, Msz/128), 256>>>(Msz, DM, DI,
        (const float*)p_y, DI, out_proj_w, DI,
        (float*)p_feat, DM, nullptr, (const float*)p_feat, DM, 0);

    // 11) post-LN
    ln_kernel<<<Msz, 256>>>((const float*)p_feat, post_g, post_b, (float*)p_hn);

    // 12) mean pool
    pool_kernel<<<Bsz, 256>>>();

    // 13) classifier
    fine_kernel<<<Bsz, 64>>>(fine_w, fine_b, out);

    (void)sym_addr; (void)in_sizes; (void)n_in; (void)out_size;
}

// round 2
// speedup vs baseline: 1.2451x; 1.2451x over previous
#include <cuda_runtime.h>
#include <cuda_bf16.h>
#include <cstdint>

// ---------------- problem constants ----------------
#define Bsz 8
#define Tsz 1024
#define Msz (Bsz*Tsz)        // 8192
#define DM  256
#define DI  512
#define DS  16
#define DTR 16
#define NCLS 60
#define KF  232              // 225 padded to mult of 8
#define CH  16               // scan chunk (timesteps staged per block iter)

// ---------------- device scratch ----------------
__device__ float g_featK[Msz*KF];
__device__ float g_embed_wp[DM*KF];
__device__ float g_feat[Msz*DM];
__device__ float g_hn[Msz*DM];
__device__ float g_xz[(size_t)Msz*1024];
__device__ float g_xmc[Msz*DI];
__device__ float g_dbl[Msz*48];
__device__ float g_delta[Msz*DI];
__device__ float g_y[Msz*DI];
__device__ float g_pooled[Bsz*DM];

__device__ __forceinline__ float softplusf(float v){
    return v > 20.f ? v : log1pf(expf(v));
}
__device__ __forceinline__ float siluf(float v){
    return v / (1.f + __expf(-v));
}

// ---------------- feature construction ----------------
__global__ void feat_kernel(const float* __restrict__ x){
    int i = blockIdx.x*blockDim.x + threadIdx.x;
    if (i >= Msz*25) return;
    int j = i % 25;
    int m = i / 25;
    int t = m & (Tsz-1);
    const float* xr  = x + (size_t)m*75;
    const float* xr1 = xr - 75;
    const float* xr2 = xr - 150;
    float* o = g_featK + (size_t)m*KF + j*9;
    #pragma unroll
    for (int c = 0; c < 3; c++){
        float p0 = xr[j*3+c]  - xr[c];
        float p1 = (t>=1) ? (xr1[j*3+c] - xr1[c]) : 0.f;
        float p2 = (t>=2) ? (xr2[j*3+c] - xr2[c]) : 0.f;
        float vel   = (t>=1) ? (p0 - p1) : 0.f;
        float velm1 = (t>=2) ? (p1 - p2) : 0.f;
        float acc   = (t>=1) ? (vel - velm1) : 0.f;
        o[c]   = p0;
        o[3+c] = vel;
        o[6+c] = acc;
    }
    if (j == 0){
        #pragma unroll
        for (int k = 225; k < KF; k++) g_featK[(size_t)m*KF + k] = 0.f;
    }
}

__global__ void padw_kernel(const float* __restrict__ ew){
    int i = blockIdx.x*blockDim.x + threadIdx.x;
    if (i >= DM*KF) return;
    int n = i / KF, k = i % KF;
    g_embed_wp[i] = (k < 225) ? ew[n*225 + k] : 0.f;
}

// ---------------- double-buffered SGEMM (NT): C[M,N] = A[M,K] @ W[N,K]^T ----------------
__global__ __launch_bounds__(256) void sgemm_nt(
    int M, int N, int K,
    const float* __restrict__ A, int lda,
    const float* __restrict__ W, int ldw,
    float* __restrict__ C, int ldc,
    const float* __restrict__ bias,
    const float* __restrict__ addC, int ldadd,
    int act)
{
    __shared__ float As[2][8][132];
    __shared__ float Ws[2][8][132];
    const int bm = blockIdx.y * 128;
    const int bn = blockIdx.x * 128;
    const int tid = threadIdx.x;
    const int lr = tid >> 1;          // load row in tile (0..127)
    const int lc = (tid & 1) * 4;     // load col offset (0 or 4)
    const int tr = (tid >> 4) << 3;   // compute row offset
    const int tc = (tid & 15) << 3;   // compute col offset

    float acc[8][8];
    #pragma unroll
    for (int i = 0; i < 8; i++)
        #pragma unroll
        for (int j = 0; j < 8; j++) acc[i][j] = 0.f;

    const float* Aptr = A + (size_t)(bm + lr) * lda + lc;
    const bool wvalid = (bn + lr) < N;
    const float* Wptr = W + (size_t)(bn + lr) * ldw + lc;
    const float4 f40 = make_float4(0.f,0.f,0.f,0.f);

    // prologue: tile 0
    {
        float4 av = *(const float4*)(Aptr);
        float4 wv = wvalid ? *(const float4*)(Wptr) : f40;
        As[0][lc+0][lr]=av.x; As[0][lc+1][lr]=av.y; As[0][lc+2][lr]=av.z; As[0][lc+3][lr]=av.w;
        Ws[0][lc+0][lr]=wv.x; Ws[0][lc+1][lr]=wv.y; Ws[0][lc+2][lr]=wv.z; Ws[0][lc+3][lr]=wv.w;
    }
    __syncthreads();

    int buf = 0;
    for (int k0 = 0; k0 < K; k0 += 8){
        float4 av2, wv2;
        const bool more = (k0 + 8) < K;
        if (more){
            av2 = *(const float4*)(Aptr + k0 + 8);
            wv2 = wvalid ? *(const float4*)(Wptr + k0 + 8) : f40;
        }
        #pragma unroll
        for (int kk = 0; kk < 8; kk++){
            float ra[8], rb[8];
            *(float4*)(ra)   = *(const float4*)&As[buf][kk][tr];
            *(float4*)(ra+4) = *(const float4*)&As[buf][kk][tr+4];
            *(float4*)(rb)   = *(const float4*)&Ws[buf][kk][tc];
            *(float4*)(rb+4) = *(const float4*)&Ws[buf][kk][tc+4];
            #pragma unroll
            for (int i = 0; i < 8; i++)
                #pragma unroll
                for (int j = 0; j < 8; j++)
                    acc[i][j] = fmaf(ra[i], rb[j], acc[i][j]);
        }
        if (more){
            int nb = buf ^ 1;
            As[nb][lc+0][lr]=av2.x; As[nb][lc+1][lr]=av2.y; As[nb][lc+2][lr]=av2.z; As[nb][lc+3][lr]=av2.w;
            Ws[nb][lc+0][lr]=wv2.x; Ws[nb][lc+1][lr]=wv2.y; Ws[nb][lc+2][lr]=wv2.z; Ws[nb][lc+3][lr]=wv2.w;
        }
        __syncthreads();
        buf ^= 1;
    }

    #pragma unroll
    for (int i = 0; i < 8; i++){
        int m = bm + tr + i;
        float* crow = C + (size_t)m * ldc;
        const float* arow = addC ? addC + (size_t)m * ldadd : nullptr;
        #pragma unroll
        for (int j = 0; j < 8; j++){
            int nn = bn + tc + j;
            if (nn < N){
                float v = acc[i][j];
                if (bias) v += bias[nn];
                if (act)  v  = softplusf(v);
                if (arow) v += arow[nn];
                crow[nn] = v;
            }
        }
    }
}

// ---------------- layernorm over last dim = 256 ----------------
__global__ __launch_bounds__(256) void ln_kernel(
    const float* __restrict__ in, const float* __restrict__ g,
    const float* __restrict__ bta, float* __restrict__ out)
{
    int m = blockIdx.x;
    int c = threadIdx.x;
    float v = in[(size_t)m*DM + c];
    float s = v, q = v*v;
    #pragma unroll
    for (int o = 16; o; o >>= 1){
        s += __shfl_xor_sync(0xffffffffu, s, o);
        q += __shfl_xor_sync(0xffffffffu, q, o);
    }
    __shared__ float red[2][8];
    int w = c >> 5, l = c & 31;
    if (l == 0){ red[0][w] = s; red[1][w] = q; }
    __syncthreads();
    float S = 0.f, Q = 0.f;
    #pragma unroll
    for (int i = 0; i < 8; i++){ S += red[0][i]; Q += red[1][i]; }
    float mu  = S * (1.f/256.f);
    float var = Q * (1.f/256.f) - mu*mu;
    float inv = rsqrtf(var + 1e-5f);
    out[(size_t)m*DM + c] = (v - mu) * inv * g[c] + bta[c];
}

// ---------------- causal depthwise conv (k=4) + silu ----------------
__global__ void conv_silu_kernel(const float* __restrict__ cw, const float* __restrict__ cb){
    int i = blockIdx.x*blockDim.x + threadIdx.x;   // over Msz*DI
    int d = i & (DI-1);
    int m = i >> 9;
    int t = m & (Tsz-1);
    float w0 = cw[d*4+0], w1 = cw[d*4+1], w2 = cw[d*4+2], w3 = cw[d*4+3];
    float a = cb[d];
    a = fmaf(w3, g_xz[(size_t)m*1024 + d], a);
    if (t >= 1) a = fmaf(w2, g_xz[(size_t)(m-1)*1024 + d], a);
    if (t >= 2) a = fmaf(w1, g_xz[(size_t)(m-2)*1024 + d], a);
    if (t >= 3) a = fmaf(w0, g_xz[(size_t)(m-3)*1024 + d], a);
    g_xmc[i] = siluf(a);
}

// ---------------- selective scan, block-staged, double-buffered, gate fused ----------------
// grid = Bsz*32 blocks; block = 256 threads = 8 warps; block covers 16 channels d.
// Each warp owns 2 channels (16 state lanes each, n = lane&15).
__global__ __launch_bounds__(256) void scan_kernel(
    const float* __restrict__ A_log, const float* __restrict__ Dp)
{
    __shared__ float s_dv [2][CH][16];
    __shared__ float s_uv [2][CH][16];
    __shared__ float s_res[2][CH][16];
    __shared__ float s_bc [2][CH][32];
    __shared__ float s_y  [CH][16];

    const int tid  = threadIdx.x;
    const int lane = tid & 31;
    const int warp = tid >> 5;
    const int b     = blockIdx.x >> 5;
    const int dbase = (blockIdx.x & 31) * 16;
    const int dloc  = warp*2 + (lane >> 4);
    const int d     = dbase + dloc;
    const int n     = lane & 15;

    const float a  = -expf(A_log[d*DS + n]);
    const float Dd = Dp[d];
    const size_t base = (size_t)b * Tsz;

    // staging indices
    const int lt = tid >> 4;      // 0..15 (timestep within chunk)
    const int ld = tid & 15;      // 0..15 (channel within block)
    const int bt = tid >> 5;      // 0..7
    const int bcc = tid & 31;     // 0..31

    // prologue: stage chunk 0
    {
        size_t row = base + lt;
        s_dv [0][lt][ld] = g_delta[row*DI + dbase + ld];
        s_uv [0][lt][ld] = g_xmc [row*DI + dbase + ld];
        s_res[0][lt][ld] = g_xz  [row*1024 + 512 + dbase + ld];
        s_bc [0][bt  ][bcc] = g_dbl[(base + bt    )*48 + 16 + bcc];
        s_bc [0][bt+8][bcc] = g_dbl[(base + bt + 8)*48 + 16 + bcc];
    }
    __syncthreads();

    float h = 0.f;
    int buf = 0;
    for (int tcb = 0; tcb < Tsz; tcb += CH){
        const bool more = (tcb + CH) < Tsz;
        float r_dv=0.f, r_uv=0.f, r_res=0.f, r_bc0=0.f, r_bc1=0.f;
        if (more){
            size_t row = base + tcb + CH + lt;
            r_dv  = g_delta[row*DI + dbase + ld];
            r_uv  = g_xmc [row*DI + dbase + ld];
            r_res = g_xz  [row*1024 + 512 + dbase + ld];
            r_bc0 = g_dbl[(base + tcb + CH + bt    )*48 + 16 + bcc];
            r_bc1 = g_dbl[(base + tcb + CH + bt + 8)*48 + 16 + bcc];
        }
        #pragma unroll
        for (int i = 0; i < CH; i++){
            float dv = s_dv[buf][i][dloc];
            float uv = s_uv[buf][i][dloc];
            float Bn = s_bc[buf][i][n];
            float Cn = s_bc[buf][i][16 + n];
            float dA = __expf(dv * a);
            h = fmaf(dA, h, dv * Bn * uv);
            float p = h * Cn;
            p += __shfl_xor_sync(0xffffffffu, p, 1);
            p += __shfl_xor_sync(0xffffffffu, p, 2);
            p += __shfl_xor_sync(0xffffffffu, p, 4);
            p += __shfl_xor_sync(0xffffffffu, p, 8);
            if (n == 0){
                float rv = s_res[buf][i][dloc];
                s_y[i][dloc] = fmaf(uv, Dd, p) * siluf(rv);   // gate fused
            }
        }
        __syncthreads();   // s_y complete; buf^1 free for refill
        if (more){
            int nb = buf ^ 1;
            s_dv [nb][lt][ld] = r_dv;
            s_uv [nb][lt][ld] = r_uv;
            s_res[nb][lt][ld] = r_res;
            s_bc [nb][bt  ][bcc] = r_bc0;
            s_bc [nb][bt+8][bcc] = r_bc1;
        }
        g_y[(base + tcb + lt)*DI + dbase + ld] = s_y[lt][ld];  // coalesced store
        __syncthreads();
        buf ^= 1;
    }
}

// ---------------- mean pool over T ----------------
__global__ void pool_kernel(){
    int b = blockIdx.x;
    int c = threadIdx.x;
    const float* p = g_hn + (size_t)b*Tsz*DM + c;
    float s0=0.f, s1=0.f, s2=0.f, s3=0.f;
    for (int t = 0; t < Tsz; t += 4){
        s0 += p[(size_t)(t+0)*DM];
        s1 += p[(size_t)(t+1)*DM];
        s2 += p[(size_t)(t+2)*DM];
        s3 += p[(size_t)(t+3)*DM];
    }
    g_pooled[b*DM + c] = (s0+s1+s2+s3) * (1.f/1024.f);
}

// ---------------- classifier head ----------------
__global__ void fine_kernel(const float* __restrict__ fw, const float* __restrict__ fb,
                            float* __restrict__ out){
    int b = blockIdx.x;
    int nn = threadIdx.x;
    if (nn >= NCLS) return;
    const float* pr = g_pooled + b*DM;
    const float* wr = fw + nn*DM;
    float s = fb[nn];
    for (int k = 0; k < DM; k++) s = fmaf(pr[k], wr[k], s);
    out[b*NCLS + nn] = s;
}

// ---------------- launch ----------------
extern "C" void kernel_launch(void* const* d_in, const int* in_sizes, int n_in,
                              void* d_out, int out_size)
{
    const float* x          = (const float*)d_in[0];
    const float* embed_w    = (const float*)d_in[1];
    const float* embed_b    = (const float*)d_in[2];
    const float* pre_g      = (const float*)d_in[3];
    const float* pre_b      = (const float*)d_in[4];
    const float* in_proj_w  = (const float*)d_in[5];
    const float* conv_w     = (const float*)d_in[6];
    const float* conv_b     = (const float*)d_in[7];
    const float* x_proj_w   = (const float*)d_in[8];
    const float* dt_proj_w  = (const float*)d_in[9];
    const float* dt_proj_b  = (const float*)d_in[10];
    const float* A_log      = (const float*)d_in[11];
    const float* Dp         = (const float*)d_in[12];
    const float* out_proj_w = (const float*)d_in[13];
    const float* post_g     = (const float*)d_in[14];
    const float* post_b     = (const float*)d_in[15];
    const float* fine_w     = (const float*)d_in[16];
    const float* fine_b     = (const float*)d_in[17];
    float* out = (float*)d_out;

    void *p_featK, *p_ewp, *p_feat, *p_hn, *p_xz, *p_xmc, *p_dbl, *p_delta, *p_y;
    cudaGetSymbolAddress(&p_featK, g_featK);
    cudaGetSymbolAddress(&p_ewp,   g_embed_wp);
    cudaGetSymbolAddress(&p_feat,  g_feat);
    cudaGetSymbolAddress(&p_hn,    g_hn);
    cudaGetSymbolAddress(&p_xz,    g_xz);
    cudaGetSymbolAddress(&p_xmc,   g_xmc);
    cudaGetSymbolAddress(&p_dbl,   g_dbl);
    cudaGetSymbolAddress(&p_delta, g_delta);
    cudaGetSymbolAddress(&p_y,     g_y);

    // 1) features + padded weights
    padw_kernel<<<(DM*KF + 255)/256, 256>>>(embed_w);
    feat_kernel<<<(Msz*25 + 255)/256, 256>>>(x);

    // 2) embed GEMM: feat = featK @ embed_wp^T + embed_b
    sgemm_nt<<<dim3(2, Msz/128), 256>>>(Msz, DM, KF,
        (const float*)p_featK, KF, (const float*)p_ewp, KF,
        (float*)p_feat, DM, embed_b, nullptr, 0, 0);

    // 3) pre-LN
    ln_kernel<<<Msz, 256>>>((const float*)p_feat, pre_g, pre_b, (float*)p_hn);

    // 4) in_proj GEMM: xz = hn @ in_proj_w^T
    sgemm_nt<<<dim3(8, Msz/128), 256>>>(Msz, 1024, DM,
        (const float*)p_hn, DM, in_proj_w, DM,
        (float*)p_xz, 1024, nullptr, nullptr, 0, 0);

    // 5) depthwise conv + silu
    conv_silu_kernel<<<(Msz*DI)/256, 256>>>(conv_w, conv_b);

    // 6) x_proj GEMM: dbl = xmc @ x_proj_w^T
    sgemm_nt<<<dim3(1, Msz/128), 256>>>(Msz, 48, DI,
        (const float*)p_xmc, DI, x_proj_w, DI,
        (float*)p_dbl, 48, nullptr, nullptr, 0, 0);

    // 7) dt_proj GEMM + softplus: delta = softplus(dt @ dt_proj_w^T + b)
    sgemm_nt<<<dim3(4, Msz/128), 256>>>(Msz, DI, DTR,
        (const float*)p_dbl, 48, dt_proj_w, DTR,
        (float*)p_delta, DI, dt_proj_b, nullptr, 0, 1);

    // 8) selective scan (gate fused)
    scan_kernel<<<Bsz*32, 256>>>(A_log, Dp);

    // 9) out_proj GEMM + residual: feat = feat + y @ out_proj_w^T
    sgemm_nt<<<dim3(2, Msz/128), 256>>>(Msz, DM, DI,
        (const float*)p_y, DI, out_proj_w, DI,
        (float*)p_feat, DM, nullptr, (const float*)p_feat, DM, 0);

    // 10) post-LN
    ln_kernel<<<Msz, 256>>>((const float*)p_feat, post_g, post_b, (float*)p_hn);

    // 11) mean pool
    pool_kernel<<<Bsz, 256>>>();

    // 12) classifier
    fine_kernel<<<Bsz, 64>>>(fine_w, fine_b, out);

    (void)in_sizes; (void)n_in; (void)out_size;
}

// round 4
// speedup vs baseline: 1.7854x; 1.4340x over previous
#include <cuda_runtime.h>
#include <cuda_bf16.h>
#include <cstdint>

// ---------------- problem constants ----------------
#define Bsz 8
#define Tsz 1024
#define Msz (Bsz*Tsz)        // 8192
#define DM  256
#define DI  512
#define DS  16
#define NCLS 60
#define KF  256              // 225 padded to 256 (zero-filled)
#define CH  16               // scan chunk

// ---------------- device scratch ----------------
__device__ float g_featK[Msz*KF];
__device__ float g_embed_wp[DM*KF];
__device__ float g_feat[Msz*DM];
__device__ float g_hn[Msz*DM];
__device__ float g_xz[(size_t)Msz*1024];
__device__ float g_xmc[Msz*DI];
__device__ float g_dbl[Msz*48];
__device__ float g_delta[Msz*DI];
__device__ float g_y[Msz*DI];
__device__ float g_pooled[Bsz*DM];

__device__ __forceinline__ float softplusf(float v){
    return v > 20.f ? v : log1pf(expf(v));
}
__device__ __forceinline__ float siluf(float v){
    return v / (1.f + __expf(-v));
}

__device__ __forceinline__ uint32_t smem_u32(const void* p){
    uint32_t a;
    asm("{ .reg .u64 t; cvta.to.shared.u64 t, %1; cvt.u32.u64 %0, t; }" : "=r"(a) : "l"(p));
    return a;
}

// split fp32 pair -> packed bf16 hi / lo
__device__ __forceinline__ uint32_t split2(float a, float b, uint32_t& lo_out){
    __nv_bfloat16 ah = __float2bfloat16(a);
    __nv_bfloat16 bh = __float2bfloat16(b);
    __nv_bfloat16 al = __float2bfloat16(a - __bfloat162float(ah));
    __nv_bfloat16 bl = __float2bfloat16(b - __bfloat162float(bh));
    lo_out = (uint32_t)__bfloat16_as_ushort(al) | ((uint32_t)__bfloat16_as_ushort(bl) << 16);
    return  (uint32_t)__bfloat16_as_ushort(ah) | ((uint32_t)__bfloat16_as_ushort(bh) << 16);
}

__device__ __forceinline__ void mma16816(float* d, const uint32_t* a, const uint32_t* b){
    asm volatile(
        "mma.sync.aligned.m16n8k16.row.col.f32.bf16.bf16.f32 "
        "{%0,%1,%2,%3}, {%4,%5,%6,%7}, {%8,%9}, {%0,%1,%2,%3};"
        : "+f"(d[0]), "+f"(d[1]), "+f"(d[2]), "+f"(d[3])
        : "r"(a[0]), "r"(a[1]), "r"(a[2]), "r"(a[3]), "r"(b[0]), "r"(b[1]));
}
__device__ __forceinline__ void ldsm4(uint32_t* r, uint32_t addr){
    asm volatile("ldmatrix.sync.aligned.m8n8.x4.shared.b16 {%0,%1,%2,%3}, [%4];"
        : "=r"(r[0]), "=r"(r[1]), "=r"(r[2]), "=r"(r[3]) : "r"(addr));
}
__device__ __forceinline__ void ldsm2(uint32_t* r, uint32_t addr){
    asm volatile("ldmatrix.sync.aligned.m8n8.x2.shared.b16 {%0,%1}, [%2];"
        : "=r"(r[0]), "=r"(r[1]) : "r"(addr));
}

// ---------------- tensor-core (HMMA) split-bf16 GEMM (NT-variant) ----------------
// C[M,N] = A[M,K] @ W[N,K]^T ; block tile 128 x NT, 8 warps (2 M x 4 N).
// Accuracy: acc += Ah*Wh + Ah*Wl + Al*Wh  (fp32 accumulate in registers).
template<int NT, int KC>
__global__ __launch_bounds__(256) void gemm_mma(
    int K, int N,
    const float* __restrict__ A, int lda,
    const float* __restrict__ W, int ldw,
    float* __restrict__ C, int ldc,
    const float* __restrict__ bias,
    const float* __restrict__ addC, int ldadd,
    int act)
{
    extern __shared__ char smem[];
    constexpr int LDT = KC + 8;                 // bf16 elems per padded row
    constexpr int NWT = NT/32;                  // 8-wide n-tiles per warp
    const uint32_t sb = smem_u32(smem);
    // layout: [A_hi 128*LDT][A_lo 128*LDT][W_hi NT*LDT][W_lo NT*LDT] (bf16)
    __nv_bfloat16* sAh = (__nv_bfloat16*)smem;
    __nv_bfloat16* sAl = sAh + 128*LDT;
    __nv_bfloat16* sWh = sAl + 128*LDT;
    __nv_bfloat16* sWl = sWh + NT*LDT;

    const int tid  = threadIdx.x;
    const int lane = tid & 31;
    const int warp = tid >> 5;
    const int bm = blockIdx.y * 128;
    const int bn = blockIdx.x * NT;
    const int nv = min(NT, N - bn);

    const int wm = (warp & 1) * 64;
    const int wn = (warp >> 1) * (NT/4);

    float acc[4][NWT][4];
    #pragma unroll
    for (int mt = 0; mt < 4; mt++)
        #pragma unroll
        for (int nt = 0; nt < NWT; nt++)
            #pragma unroll
            for (int i = 0; i < 4; i++) acc[mt][nt][i] = 0.f;

    // precomputed ldmatrix base offsets (bytes), kk added per step
    const int a_row = wm + (lane & 15);
    const int a_colb = (lane >> 4) * 8;
    const int b_row = wn + (lane & 7);
    const int b_colb = ((lane >> 3) & 1) * 8;

    for (int c = 0; c < K/KC; c++){
        // stage A (128 x KC) and W (NT x KC) as hi/lo bf16
        {
            const float* src = A + (size_t)bm*lda + c*KC;
            constexpr int C4 = KC/4;
            #pragma unroll 2
            for (int idx = tid; idx < 128*C4; idx += 256){
                int row = idx / C4, col = (idx - row*C4)*4;
                float4 v = *(const float4*)(src + (size_t)row*lda + col);
                uint32_t l01, l23;
                uint32_t h01 = split2(v.x, v.y, l01);
                uint32_t h23 = split2(v.z, v.w, l23);
                *(uint64_t*)(sAh + row*LDT + col) = ((uint64_t)h23<<32) | h01;
                *(uint64_t*)(sAl + row*LDT + col) = ((uint64_t)l23<<32) | l01;
            }
            const float* ws = W + (size_t)bn*ldw + c*KC;
            #pragma unroll 2
            for (int idx = tid; idx < NT*C4; idx += 256){
                int row = idx / C4, col = (idx - row*C4)*4;
                float4 v = (row < nv) ? *(const float4*)(ws + (size_t)row*ldw + col)
                                      : make_float4(0.f,0.f,0.f,0.f);
                uint32_t l01, l23;
                uint32_t h01 = split2(v.x, v.y, l01);
                uint32_t h23 = split2(v.z, v.w, l23);
                *(uint64_t*)(sWh + row*LDT + col) = ((uint64_t)h23<<32) | h01;
                *(uint64_t*)(sWl + row*LDT + col) = ((uint64_t)l23<<32) | l01;
            }
        }
        __syncthreads();

        #pragma unroll
        for (int kk = 0; kk < KC; kk += 16){
            uint32_t ah[4][4], al[4][4];
            #pragma unroll
            for (int mt = 0; mt < 4; mt++){
                uint32_t ad = sb + (uint32_t)(((a_row + mt*16)*LDT + kk + a_colb) * 2);
                ldsm4(ah[mt], ad);
                ldsm4(al[mt], ad + 128*LDT*2);
            }
            uint32_t bh[NWT][2], bl[NWT][2];
            #pragma unroll
            for (int nt = 0; nt < NWT; nt++){
                uint32_t bd = sb + (uint32_t)((256*LDT + (b_row + nt*8)*LDT + kk + b_colb) * 2);
                ldsm2(bh[nt], bd);
                ldsm2(bl[nt], bd + NT*LDT*2);
            }
            #pragma unroll
            for (int mt = 0; mt < 4; mt++)
                #pragma unroll
                for (int nt = 0; nt < NWT; nt++){
                    mma16816(acc[mt][nt], ah[mt], bh[nt]);
                    mma16816(acc[mt][nt], ah[mt], bl[nt]);
                    mma16816(acc[mt][nt], al[mt], bh[nt]);
                }
        }
        __syncthreads();
    }

    // epilogue: fragment -> global, fused bias / softplus / residual
    #pragma unroll
    for (int mt = 0; mt < 4; mt++){
        #pragma unroll
        for (int i = 0; i < 4; i++){
            int m = bm + wm + mt*16 + (lane >> 2) + (i >> 1)*8;
            #pragma unroll
            for (int nt = 0; nt < NWT; nt++){
                int n = wn + nt*8 + (lane & 3)*2 + (i & 1);
                if (n < nv){
                    int gn = bn + n;
                    float v = acc[mt][nt][i];
                    if (bias) v += bias[gn];
                    if (act)  v  = softplusf(v);
                    if (addC) v += addC[(size_t)m*ldadd + gn];
                    C[(size_t)m*ldc + gn] = v;
                }
            }
        }
    }
}

// ---------------- feature construction ----------------
__global__ void feat_kernel(const float* __restrict__ x){
    int i = blockIdx.x*blockDim.x + threadIdx.x;
    if (i >= Msz*25) return;
    int j = i % 25;
    int m = i / 25;
    int t = m & (Tsz-1);
    const float* xr  = x + (size_t)m*75;
    const float* xr1 = xr - 75;
    const float* xr2 = xr - 150;
    float* o = g_featK + (size_t)m*KF + j*9;
    #pragma unroll
    for (int c = 0; c < 3; c++){
        float p0 = xr[j*3+c]  - xr[c];
        float p1 = (t>=1) ? (xr1[j*3+c] - xr1[c]) : 0.f;
        float p2 = (t>=2) ? (xr2[j*3+c] - xr2[c]) : 0.f;
        float vel   = (t>=1) ? (p0 - p1) : 0.f;
        float velm1 = (t>=2) ? (p1 - p2) : 0.f;
        float acc   = (t>=1) ? (vel - velm1) : 0.f;
        o[c]   = p0;
        o[3+c] = vel;
        o[6+c] = acc;
    }
    if (j == 0){
        for (int k = 225; k < KF; k++) g_featK[(size_t)m*KF + k] = 0.f;
    }
}

__global__ void padw_kernel(const float* __restrict__ ew){
    int i = blockIdx.x*blockDim.x + threadIdx.x;
    if (i >= DM*KF) return;
    int n = i / KF, k = i % KF;
    g_embed_wp[i] = (k < 225) ? ew[n*225 + k] : 0.f;
}

// ---------------- layernorm over last dim = 256 ----------------
__global__ __launch_bounds__(256) void ln_kernel(
    const float* __restrict__ in, const float* __restrict__ g,
    const float* __restrict__ bta, float* __restrict__ out)
{
    int m = blockIdx.x;
    int c = threadIdx.x;
    float v = in[(size_t)m*DM + c];
    float s = v, q = v*v;
    #pragma unroll
    for (int o = 16; o; o >>= 1){
        s += __shfl_xor_sync(0xffffffffu, s, o);
        q += __shfl_xor_sync(0xffffffffu, q, o);
    }
    __shared__ float red[2][8];
    int w = c >> 5, l = c & 31;
    if (l == 0){ red[0][w] = s; red[1][w] = q; }
    __syncthreads();
    float S = 0.f, Q = 0.f;
    #pragma unroll
    for (int i = 0; i < 8; i++){ S += red[0][i]; Q += red[1][i]; }
    float mu  = S * (1.f/256.f);
    float var = Q * (1.f/256.f) - mu*mu;
    float inv = rsqrtf(var + 1e-5f);
    out[(size_t)m*DM + c] = (v - mu) * inv * g[c] + bta[c];
}

// ---------------- causal depthwise conv (k=4) + silu ----------------
__global__ void conv_silu_kernel(const float* __restrict__ cw, const float* __restrict__ cb){
    int i = blockIdx.x*blockDim.x + threadIdx.x;
    int d = i & (DI-1);
    int m = i >> 9;
    int t = m & (Tsz-1);
    float w0 = cw[d*4+0], w1 = cw[d*4+1], w2 = cw[d*4+2], w3 = cw[d*4+3];
    float a = cb[d];
    a = fmaf(w3, g_xz[(size_t)m*1024 + d], a);
    if (t >= 1) a = fmaf(w2, g_xz[(size_t)(m-1)*1024 + d], a);
    if (t >= 2) a = fmaf(w1, g_xz[(size_t)(m-2)*1024 + d], a);
    if (t >= 3) a = fmaf(w0, g_xz[(size_t)(m-3)*1024 + d], a);
    g_xmc[i] = siluf(a);
}

// ---------------- selective scan, block-staged, double-buffered, gate fused ----------------
__global__ __launch_bounds__(256) void scan_kernel(
    const float* __restrict__ A_log, const float* __restrict__ Dp)
{
    __shared__ float s_dv [2][CH][16];
    __shared__ float s_uv [2][CH][16];
    __shared__ float s_res[2][CH][16];
    __shared__ float s_bc [2][CH][32];
    __shared__ float s_y  [CH][16];

    const int tid  = threadIdx.x;
    const int lane = tid & 31;
    const int warp = tid >> 5;
    const int b     = blockIdx.x >> 5;
    const int dbase = (blockIdx.x & 31) * 16;
    const int dloc  = warp*2 + (lane >> 4);
    const int d     = dbase + dloc;
    const int n     = lane & 15;

    const float a  = -expf(A_log[d*DS + n]);
    const float Dd = Dp[d];
    const size_t base = (size_t)b * Tsz;

    const int lt = tid >> 4;
    const int ld = tid & 15;
    const int bt = tid >> 5;
    const int bcc = tid & 31;

    {
        size_t row = base + lt;
        s_dv [0][lt][ld] = g_delta[row*DI + dbase + ld];
        s_uv [0][lt][ld] = g_xmc [row*DI + dbase + ld];
        s_res[0][lt][ld] = g_xz  [row*1024 + 512 + dbase + ld];
        s_bc [0][bt  ][bcc] = g_dbl[(base + bt    )*48 + 16 + bcc];
        s_bc [0][bt+8][bcc] = g_dbl[(base + bt + 8)*48 + 16 + bcc];
    }
    __syncthreads();

    float h = 0.f;
    int buf = 0;
    for (int tcb = 0; tcb < Tsz; tcb += CH){
        const bool more = (tcb + CH) < Tsz;
        float r_dv=0.f, r_uv=0.f, r_res=0.f, r_bc0=0.f, r_bc1=0.f;
        if (more){
            size_t row = base + tcb + CH + lt;
            r_dv  = g_delta[row*DI + dbase + ld];
            r_uv  = g_xmc [row*DI + dbase + ld];
            r_res = g_xz  [row*1024 + 512 + dbase + ld];
            r_bc0 = g_dbl[(base + tcb + CH + bt    )*48 + 16 + bcc];
            r_bc1 = g_dbl[(base + tcb + CH + bt + 8)*48 + 16 + bcc];
        }
        #pragma unroll
        for (int i = 0; i < CH; i++){
            float dv = s_dv[buf][i][dloc];
            float uv = s_uv[buf][i][dloc];
            float Bn = s_bc[buf][i][n];
            float Cn = s_bc[buf][i][16 + n];
            float dA = __expf(dv * a);
            h = fmaf(dA, h, dv * Bn * uv);
            float p = h * Cn;
            p += __shfl_xor_sync(0xffffffffu, p, 1);
            p += __shfl_xor_sync(0xffffffffu, p, 2);
            p += __shfl_xor_sync(0xffffffffu, p, 4);
            p += __shfl_xor_sync(0xffffffffu, p, 8);
            if (n == 0){
                float rv = s_res[buf][i][dloc];
                s_y[i][dloc] = fmaf(uv, Dd, p) * siluf(rv);
            }
        }
        __syncthreads();
        if (more){
            int nb = buf ^ 1;
            s_dv [nb][lt][ld] = r_dv;
            s_uv [nb][lt][ld] = r_uv;
            s_res[nb][lt][ld] = r_res;
            s_bc [nb][bt  ][bcc] = r_bc0;
            s_bc [nb][bt+8][bcc] = r_bc1;
        }
        g_y[(base + tcb + lt)*DI + dbase + ld] = s_y[lt][ld];
        __syncthreads();
        buf ^= 1;
    }
}

// ---------------- mean pool over T ----------------
__global__ void pool_kernel(){
    int b = blockIdx.x;
    int c = threadIdx.x;
    const float* p = g_hn + (size_t)b*Tsz*DM + c;
    float s0=0.f, s1=0.f, s2=0.f, s3=0.f;
    for (int t = 0; t < Tsz; t += 4){
        s0 += p[(size_t)(t+0)*DM];
        s1 += p[(size_t)(t+1)*DM];
        s2 += p[(size_t)(t+2)*DM];
        s3 += p[(size_t)(t+3)*DM];
    }
    g_pooled[b*DM + c] = (s0+s1+s2+s3) * (1.f/1024.f);
}

// ---------------- classifier head ----------------
__global__ void fine_kernel(const float* __restrict__ fw, const float* __restrict__ fb,
                            float* __restrict__ out){
    int b = blockIdx.x;
    int nn = threadIdx.x;
    if (nn >= NCLS) return;
    const float* pr = g_pooled + b*DM;
    const float* wr = fw + nn*DM;
    float s = fb[nn];
    for (int k = 0; k < DM; k++) s = fmaf(pr[k], wr[k], s);
    out[b*NCLS + nn] = s;
}

// ---------------- launch ----------------
extern "C" void kernel_launch(void* const* d_in, const int* in_sizes, int n_in,
                              void* d_out, int out_size)
{
    const float* x          = (const float*)d_in[0];
    const float* embed_w    = (const float*)d_in[1];
    const float* embed_b    = (const float*)d_in[2];
    const float* pre_g      = (const float*)d_in[3];
    const float* pre_b      = (const float*)d_in[4];
    const float* in_proj_w  = (const float*)d_in[5];
    const float* conv_w     = (const float*)d_in[6];
    const float* conv_b     = (const float*)d_in[7];
    const float* x_proj_w   = (const float*)d_in[8];
    const float* dt_proj_w  = (const float*)d_in[9];
    const float* dt_proj_b  = (const float*)d_in[10];
    const float* A_log      = (const float*)d_in[11];
    const float* Dp         = (const float*)d_in[12];
    const float* out_proj_w = (const float*)d_in[13];
    const float* post_g     = (const float*)d_in[14];
    const float* post_b     = (const float*)d_in[15];
    const float* fine_w     = (const float*)d_in[16];
    const float* fine_b     = (const float*)d_in[17];
    float* out = (float*)d_out;

    void *p_featK, *p_ewp, *p_feat, *p_hn, *p_xz, *p_xmc, *p_dbl, *p_delta, *p_y;
    cudaGetSymbolAddress(&p_featK, g_featK);
    cudaGetSymbolAddress(&p_ewp,   g_embed_wp);
    cudaGetSymbolAddress(&p_feat,  g_feat);
    cudaGetSymbolAddress(&p_hn,    g_hn);
    cudaGetSymbolAddress(&p_xz,    g_xz);
    cudaGetSymbolAddress(&p_xmc,   g_xmc);
    cudaGetSymbolAddress(&p_dbl,   g_dbl);
    cudaGetSymbolAddress(&p_delta, g_delta);
    cudaGetSymbolAddress(&p_y,     g_y);

    // dynamic SMEM sizes: (2*128 + 2*NT) * (KC+8) * 2 bytes
    const int SM_64_64 = (2*128 + 2*64) * (64+8) * 2;   // 55296
    const int SM_64_16 = (2*128 + 2*64) * (16+8) * 2;   // 18432
    cudaFuncSetAttribute(gemm_mma<64,64>, cudaFuncAttributeMaxDynamicSharedMemorySize, SM_64_64);
    cudaFuncSetAttribute(gemm_mma<64,16>, cudaFuncAttributeMaxDynamicSharedMemorySize, SM_64_16);

    // 1) features + padded weights
    padw_kernel<<<(DM*KF + 255)/256, 256>>>(embed_w);
    feat_kernel<<<(Msz*25 + 255)/256, 256>>>(x);

    // 2) embed GEMM: feat = featK @ embed_wp^T + embed_b
    gemm_mma<64,64><<<dim3(DM/64, Msz/128), 256, SM_64_64>>>(
        KF, DM, (const float*)p_featK, KF, (const float*)p_ewp, KF,
        (float*)p_feat, DM, embed_b, nullptr, 0, 0);

    // 3) pre-LN
    ln_kernel<<<Msz, 256>>>((const float*)p_feat, pre_g, pre_b, (float*)p_hn);

    // 4) in_proj GEMM: xz = hn @ in_proj_w^T
    gemm_mma<64,64><<<dim3(1024/64, Msz/128), 256, SM_64_64>>>(
        DM, 1024, (const float*)p_hn, DM, in_proj_w, DM,
        (float*)p_xz, 1024, nullptr, nullptr, 0, 0);

    // 5) depthwise conv + silu
    conv_silu_kernel<<<(Msz*DI)/256, 256>>>(conv_w, conv_b);

    // 6) x_proj GEMM: dbl = xmc @ x_proj_w^T  (N=48, one 64-tile)
    gemm_mma<64,64><<<dim3(1, Msz/128), 256, SM_64_64>>>(
        DI, 48, (const float*)p_xmc, DI, x_proj_w, DI,
        (float*)p_dbl, 48, nullptr, nullptr, 0, 0);

    // 7) dt_proj GEMM + softplus: delta = softplus(dbl[:, :16] @ dt_proj_w^T + b)
    gemm_mma<64,16><<<dim3(DI/64, Msz/128), 256, SM_64_16>>>(
        16, DI, (const float*)p_dbl, 48, dt_proj_w, 16,
        (float*)p_delta, DI, dt_proj_b, nullptr, 0, 1);

    // 8) selective scan (gate fused)
    scan_kernel<<<Bsz*32, 256>>>(A_log, Dp);

    // 9) out_proj GEMM + residual: feat = feat + y @ out_proj_w^T
    gemm_mma<64,64><<<dim3(DM/64, Msz/128), 256, SM_64_64>>>(
        DI, DM, (const float*)p_y, DI, out_proj_w, DI,
        (float*)p_feat, DM, nullptr, (const float*)p_feat, DM, 0);

    // 10) post-LN
    ln_kernel<<<Msz, 256>>>((const float*)p_feat, post_g, post_b, (float*)p_hn);

    // 11) mean pool
    pool_kernel<<<Bsz, 256>>>();

    // 12) classifier
    fine_kernel<<<Bsz, 64>>>(fine_w, fine_b, out);

    (void)in_sizes; (void)n_in; (void)out_size;
}

// round 6
// speedup vs baseline: 1.8520x; 1.0373x over previous
#include <cuda_runtime.h>
#include <cuda_bf16.h>
#include <cstdint>

// ---------------- problem constants ----------------
#define Bsz 8
#define Tsz 1024
#define Msz (Bsz*Tsz)        // 8192
#define DM  256
#define DI  512
#define DS  16
#define NCLS 60
#define KF  256              // 225 padded to 256 (zero-filled)
#define CH  16               // scan chunk

// ---------------- device scratch ----------------
__device__ __nv_bfloat16 g_fk_hi[Msz*KF];
__device__ __nv_bfloat16 g_fk_lo[Msz*KF];
__device__ float g_feat[Msz*DM];
__device__ float g_hn[Msz*DM];
__device__ __nv_bfloat16 g_hn_hi[Msz*DM];
__device__ __nv_bfloat16 g_hn_lo[Msz*DM];
__device__ float g_xz[(size_t)Msz*1024];
__device__ float g_xmc[Msz*DI];
__device__ __nv_bfloat16 g_xm_hi[Msz*DI];
__device__ __nv_bfloat16 g_xm_lo[Msz*DI];
__device__ float g_dbl[Msz*48];
__device__ __nv_bfloat16 g_dt_hi[Msz*16];
__device__ __nv_bfloat16 g_dt_lo[Msz*16];
__device__ float g_delta[Msz*DI];
__device__ __nv_bfloat16 g_yh[Msz*DI];
__device__ __nv_bfloat16 g_yl[Msz*DI];
__device__ float g_pooled[Bsz*DM];
// weights (bf16 hi/lo, padded)
__device__ __nv_bfloat16 g_wemb_hi[DM*KF],   g_wemb_lo[DM*KF];       // 256 x 256
__device__ __nv_bfloat16 g_win_hi[1024*DM],  g_win_lo[1024*DM];      // 1024 x 256
__device__ __nv_bfloat16 g_wxp_hi[64*DI],    g_wxp_lo[64*DI];        // 48->64 x 512
__device__ __nv_bfloat16 g_wdt_hi[DI*16],    g_wdt_lo[DI*16];        // 512 x 16
__device__ __nv_bfloat16 g_wout_hi[DM*DI],   g_wout_lo[DM*DI];       // 256 x 512

__device__ __forceinline__ float softplusf(float v){
    return v > 20.f ? v : log1pf(expf(v));
}
__device__ __forceinline__ float siluf(float v){
    return v / (1.f + __expf(-v));
}
__device__ __forceinline__ void split1(float v, __nv_bfloat16& h, __nv_bfloat16& l){
    h = __float2bfloat16(v);
    l = __float2bfloat16(v - __bfloat162float(h));
}
__device__ __forceinline__ uint32_t smem_u32(const void* p){
    uint32_t a;
    asm("{ .reg .u64 t; cvta.to.shared.u64 t, %1; cvt.u32.u64 %0, t; }" : "=r"(a) : "l"(p));
    return a;
}
__device__ __forceinline__ void cp16(uint32_t dst, const void* src){
    asm volatile("cp.async.cg.shared.global [%0], [%1], 16;" :: "r"(dst), "l"(src));
}
__device__ __forceinline__ void mma16816(float* d, const uint32_t* a, const uint32_t* b){
    asm volatile(
        "mma.sync.aligned.m16n8k16.row.col.f32.bf16.bf16.f32 "
        "{%0,%1,%2,%3}, {%4,%5,%6,%7}, {%8,%9}, {%0,%1,%2,%3};"
        : "+f"(d[0]), "+f"(d[1]), "+f"(d[2]), "+f"(d[3])
        : "r"(a[0]), "r"(a[1]), "r"(a[2]), "r"(a[3]), "r"(b[0]), "r"(b[1]));
}
__device__ __forceinline__ void ldsm4(uint32_t* r, uint32_t addr){
    asm volatile("ldmatrix.sync.aligned.m8n8.x4.shared.b16 {%0,%1,%2,%3}, [%4];"
        : "=r"(r[0]), "=r"(r[1]), "=r"(r[2]), "=r"(r[3]) : "r"(addr));
}
__device__ __forceinline__ void ldsm2(uint32_t* r, uint32_t addr){
    asm volatile("ldmatrix.sync.aligned.m8n8.x2.shared.b16 {%0,%1}, [%2];"
        : "=r"(r[0]), "=r"(r[1]) : "r"(addr));
}

// ---------------- weight split/pad: fp32 [Nsrc x Ksrc] -> bf16 hi/lo [Npad x Kpad] ----------------
__global__ void splitw_kernel(const float* __restrict__ src,
                              __nv_bfloat16* __restrict__ hi, __nv_bfloat16* __restrict__ lo,
                              int Nsrc, int Ksrc, int Kpad, int total){
    int i = blockIdx.x*256 + threadIdx.x;
    if (i >= total) return;
    int n = i / Kpad, k = i - n*Kpad;
    float v = (n < Nsrc && k < Ksrc) ? src[(size_t)n*Ksrc + k] : 0.f;
    __nv_bfloat16 h, l; split1(v, h, l);
    hi[i] = h; lo[i] = l;
}

// dbl[:, :16] -> dt hi/lo
__global__ void split_dt_kernel(){
    int i = blockIdx.x*256 + threadIdx.x;   // over Msz*16
    int row = i >> 4, k = i & 15;
    float v = g_dbl[(size_t)row*48 + k];
    __nv_bfloat16 h, l; split1(v, h, l);
    g_dt_hi[i] = h; g_dt_lo[i] = l;
}

// ---------------- feature construction (writes bf16 hi/lo directly) ----------------
__global__ void feat_kernel(const float* __restrict__ x){
    int i = blockIdx.x*blockDim.x + threadIdx.x;
    if (i >= Msz*25) return;
    int j = i % 25;
    int m = i / 25;
    int t = m & (Tsz-1);
    const float* xr  = x + (size_t)m*75;
    const float* xr1 = xr - 75;
    const float* xr2 = xr - 150;
    size_t ob = (size_t)m*KF + j*9;
    #pragma unroll
    for (int c = 0; c < 3; c++){
        float p0 = xr[j*3+c]  - xr[c];
        float p1 = (t>=1) ? (xr1[j*3+c] - xr1[c]) : 0.f;
        float p2 = (t>=2) ? (xr2[j*3+c] - xr2[c]) : 0.f;
        float vel   = (t>=1) ? (p0 - p1) : 0.f;
        float velm1 = (t>=2) ? (p1 - p2) : 0.f;
        float acc   = (t>=1) ? (vel - velm1) : 0.f;
        __nv_bfloat16 h, l;
        split1(p0, h, l);  g_fk_hi[ob+c]   = h; g_fk_lo[ob+c]   = l;
        split1(vel, h, l); g_fk_hi[ob+3+c] = h; g_fk_lo[ob+3+c] = l;
        split1(acc, h, l); g_fk_hi[ob+6+c] = h; g_fk_lo[ob+6+c] = l;
    }
    if (j == 0){
        __nv_bfloat16 z = __float2bfloat16(0.f);
        for (int k = 225; k < KF; k++){
            g_fk_hi[(size_t)m*KF + k] = z;
            g_fk_lo[(size_t)m*KF + k] = z;
        }
    }
}

// ---------------- bf16-input tensor-core GEMM (NT): C = A @ W^T, 3-pass split accumulate ----------------
// A_hi/lo: [M x K] bf16, W_hi/lo: [Npad x K] bf16 (rows >= N are zero).
// cp.async double-buffered. block 256 thr, tile 128 x NT.
template<int NT, int KC>
__global__ __launch_bounds__(256) void gemm_bf(
    int K, int N,
    const __nv_bfloat16* __restrict__ Ah_, const __nv_bfloat16* __restrict__ Al_, int lda,
    const __nv_bfloat16* __restrict__ Wh_, const __nv_bfloat16* __restrict__ Wl_, int ldw,
    float* __restrict__ C, int ldc,
    const float* __restrict__ bias,
    const float* __restrict__ addC, int ldadd,
    int act)
{
    extern __shared__ char smem[];
    constexpr int LDT = KC + 8;                   // bf16 elems per padded row
    constexpr int SBUF = (256 + 2*NT)*LDT;        // elems per buffer
    constexpr int C8 = KC/8;                      // 16B chunks per row
    constexpr int NWT = NT/32;
    const uint32_t sb = smem_u32(smem);
    const int tid = threadIdx.x, lane = tid & 31, warp = tid >> 5;
    const int bm = blockIdx.y * 128;
    const int bn = blockIdx.x * NT;
    const int nv = min(NT, N - bn);
    const int wm = (warp & 1) * 64;
    const int wn = (warp >> 1) * (NT/4);

    float acc[4][NWT][4];
    #pragma unroll
    for (int mt = 0; mt < 4; mt++)
        #pragma unroll
        for (int nt = 0; nt < NWT; nt++)
            #pragma unroll
            for (int i = 0; i < 4; i++) acc[mt][nt][i] = 0.f;

    const int a_row = wm + (lane & 15);
    const int a_colb = (lane >> 4) * 8;
    const int b_row = wn + (lane & 7);
    const int b_colb = ((lane >> 3) & 1) * 8;

    const int NC = K / KC;

    auto load_chunk = [&](int c, int bf){
        uint32_t base = sb + (uint32_t)(bf * SBUF * 2);
        const size_t koff = (size_t)c * KC;
        #pragma unroll 2
        for (int idx = tid; idx < 128*C8; idx += 256){
            int row = idx / C8, c8 = idx - row*C8;
            uint32_t d = base + (uint32_t)((row*LDT + c8*8) * 2);
            size_t s = (size_t)(bm + row)*lda + koff + c8*8;
            cp16(d,               Ah_ + s);
            cp16(d + 128*LDT*2,   Al_ + s);
        }
        #pragma unroll 2
        for (int idx = tid; idx < NT*C8; idx += 256){
            int row = idx / C8, c8 = idx - row*C8;
            uint32_t d = base + (uint32_t)(((256 + row)*LDT + c8*8) * 2);
            size_t s = (size_t)(bn + row)*ldw + koff + c8*8;
            cp16(d,               Wh_ + s);
            cp16(d + NT*LDT*2,    Wl_ + s);
        }
    };

    int buf = 0;
    load_chunk(0, 0);
    asm volatile("cp.async.commit_group;" ::: "memory");
    for (int c = 0; c < NC; c++){
        if (c + 1 < NC) load_chunk(c + 1, buf ^ 1);
        asm volatile("cp.async.commit_group;" ::: "memory");
        if (c + 1 < NC) asm volatile("cp.async.wait_group 1;" ::: "memory");
        else            asm volatile("cp.async.wait_group 0;" ::: "memory");
        __syncthreads();

        uint32_t abase = sb + (uint32_t)(buf * SBUF * 2);
        #pragma unroll
        for (int kk = 0; kk < KC; kk += 16){
            uint32_t ah[4][4], al[4][4];
            #pragma unroll
            for (int mt = 0; mt < 4; mt++){
                uint32_t ad = abase + (uint32_t)(((a_row + mt*16)*LDT + kk + a_colb) * 2);
                ldsm4(ah[mt], ad);
                ldsm4(al[mt], ad + 128*LDT*2);
            }
            uint32_t bh[NWT][2], bl[NWT][2];
            #pragma unroll
            for (int nt = 0; nt < NWT; nt++){
                uint32_t bd = abase + (uint32_t)(((256 + b_row + nt*8)*LDT + kk + b_colb) * 2);
                ldsm2(bh[nt], bd);
                ldsm2(bl[nt], bd + NT*LDT*2);
            }
            #pragma unroll
            for (int mt = 0; mt < 4; mt++)
                #pragma unroll
                for (int nt = 0; nt < NWT; nt++){
                    mma16816(acc[mt][nt], ah[mt], bh[nt]);
                    mma16816(acc[mt][nt], ah[mt], bl[nt]);
                    mma16816(acc[mt][nt], al[mt], bh[nt]);
                }
        }
        __syncthreads();
        buf ^= 1;
    }

    // epilogue: fragment -> global, fused bias / softplus / residual
    #pragma unroll
    for (int mt = 0; mt < 4; mt++){
        #pragma unroll
        for (int i = 0; i < 4; i++){
            int m = bm + wm + mt*16 + (lane >> 2) + (i >> 1)*8;
            #pragma unroll
            for (int nt = 0; nt < NWT; nt++){
                int n = wn + nt*8 + (lane & 3)*2 + (i & 1);
                if (n < nv){
                    int gn = bn + n;
                    float v = acc[mt][nt][i];
                    if (bias) v += bias[gn];
                    if (act)  v  = softplusf(v);
                    if (addC) v += addC[(size_t)m*ldadd + gn];
                    C[(size_t)m*ldc + gn] = v;
                }
            }
        }
    }
}

// ---------------- layernorm, warp-per-row (256 cols) ----------------
// mode 0: fp32 out ; mode 1: bf16 hi/lo out
__global__ __launch_bounds__(256) void ln_kernel(
    const float* __restrict__ in, const float* __restrict__ g,
    const float* __restrict__ bta, float* __restrict__ outf,
    __nv_bfloat16* __restrict__ oh, __nv_bfloat16* __restrict__ ol, int mode)
{
    int row  = blockIdx.x*8 + (threadIdx.x >> 5);
    int lane = threadIdx.x & 31;
    const float* p = in + (size_t)row*DM + lane*8;
    float4 v0 = *(const float4*)p;
    float4 v1 = *(const float4*)(p + 4);
    float va[8] = {v0.x,v0.y,v0.z,v0.w,v1.x,v1.y,v1.z,v1.w};
    float s = 0.f, q = 0.f;
    #pragma unroll
    for (int i = 0; i < 8; i++){ s += va[i]; q = fmaf(va[i], va[i], q); }
    #pragma unroll
    for (int o = 16; o; o >>= 1){
        s += __shfl_xor_sync(0xffffffffu, s, o);
        q += __shfl_xor_sync(0xffffffffu, q, o);
    }
    float mu  = s * (1.f/256.f);
    float var = q * (1.f/256.f) - mu*mu;
    float inv = rsqrtf(var + 1e-5f);
    float4 g0 = *(const float4*)(g + lane*8);
    float4 g1 = *(const float4*)(g + lane*8 + 4);
    float4 b0 = *(const float4*)(bta + lane*8);
    float4 b1 = *(const float4*)(bta + lane*8 + 4);
    float ga[8] = {g0.x,g0.y,g0.z,g0.w,g1.x,g1.y,g1.z,g1.w};
    float ba[8] = {b0.x,b0.y,b0.z,b0.w,b1.x,b1.y,b1.z,b1.w};
    float r[8];
    #pragma unroll
    for (int i = 0; i < 8; i++) r[i] = (va[i] - mu) * inv * ga[i] + ba[i];
    if (mode == 0){
        float* o = outf + (size_t)row*DM + lane*8;
        *(float4*)o       = make_float4(r[0], r[1], r[2], r[3]);
        *(float4*)(o + 4) = make_float4(r[4], r[5], r[6], r[7]);
    } else {
        size_t ob = (size_t)row*DM + lane*8;
        #pragma unroll
        for (int i = 0; i < 8; i++){
            __nv_bfloat16 h, l; split1(r[i], h, l);
            oh[ob + i] = h; ol[ob + i] = l;
        }
    }
}

// ---------------- causal depthwise conv (k=4) + silu (fp32 + bf16 hi/lo out) ----------------
__global__ void conv_silu_kernel(const float* __restrict__ cw, const float* __restrict__ cb){
    int i = blockIdx.x*blockDim.x + threadIdx.x;
    int d = i & (DI-1);
    int m = i >> 9;
    int t = m & (Tsz-1);
    float w0 = cw[d*4+0], w1 = cw[d*4+1], w2 = cw[d*4+2], w3 = cw[d*4+3];
    float a = cb[d];
    a = fmaf(w3, g_xz[(size_t)m*1024 + d], a);
    if (t >= 1) a = fmaf(w2, g_xz[(size_t)(m-1)*1024 + d], a);
    if (t >= 2) a = fmaf(w1, g_xz[(size_t)(m-2)*1024 + d], a);
    if (t >= 3) a = fmaf(w0, g_xz[(size_t)(m-3)*1024 + d], a);
    float sv = siluf(a);
    g_xmc[i] = sv;
    __nv_bfloat16 h, l; split1(sv, h, l);
    g_xm_hi[i] = h; g_xm_lo[i] = l;
}

// ---------------- selective scan: 512 blocks x 128 thr, 8 channels/block, gate fused ----------------
__global__ __launch_bounds__(128) void scan_kernel(
    const float* __restrict__ A_log, const float* __restrict__ Dp)
{
    __shared__ float s_dv [2][CH][8];
    __shared__ float s_uv [2][CH][8];
    __shared__ float s_res[2][CH][8];
    __shared__ float s_bc [2][CH][32];
    __shared__ float s_y  [CH][8];

    const int tid  = threadIdx.x;
    const int lane = tid & 31;
    const int warp = tid >> 5;
    const int b     = blockIdx.x >> 6;
    const int dbase = (blockIdx.x & 63) * 8;
    const int dloc  = warp*2 + (lane >> 4);
    const int d     = dbase + dloc;
    const int n     = lane & 15;

    const float a  = -expf(A_log[d*DS + n]);
    const float Dd = Dp[d];
    const size_t base = (size_t)b * Tsz;

    const int lt = tid >> 3;      // 0..15
    const int ld = tid & 7;       // 0..7
    const int bt = tid >> 5;      // 0..3
    const int bcc = tid & 31;

    {
        size_t row = base + lt;
        s_dv [0][lt][ld] = g_delta[row*DI + dbase + ld];
        s_uv [0][lt][ld] = g_xmc [row*DI + dbase + ld];
        s_res[0][lt][ld] = g_xz  [row*1024 + 512 + dbase + ld];
        #pragma unroll
        for (int r = 0; r < 4; r++)
            s_bc[0][bt + r*4][bcc] = g_dbl[(base + bt + r*4)*48 + 16 + bcc];
    }
    __syncthreads();

    float h = 0.f;
    int buf = 0;
    for (int tcb = 0; tcb < Tsz; tcb += CH){
        const bool more = (tcb + CH) < Tsz;
        float r_dv=0.f, r_uv=0.f, r_res=0.f, r_bc[4]={0.f,0.f,0.f,0.f};
        if (more){
            size_t row = base + tcb + CH + lt;
            r_dv  = g_delta[row*DI + dbase + ld];
            r_uv  = g_xmc [row*DI + dbase + ld];
            r_res = g_xz  [row*1024 + 512 + dbase + ld];
            #pragma unroll
            for (int r = 0; r < 4; r++)
                r_bc[r] = g_dbl[(base + tcb + CH + bt + r*4)*48 + 16 + bcc];
        }
        #pragma unroll
        for (int i = 0; i < CH; i++){
            float dv = s_dv[buf][i][dloc];
            float uv = s_uv[buf][i][dloc];
            float Bn = s_bc[buf][i][n];
            float Cn = s_bc[buf][i][16 + n];
            float dA = __expf(dv * a);
            h = fmaf(dA, h, dv * Bn * uv);
            float p = h * Cn;
            p += __shfl_xor_sync(0xffffffffu, p, 1);
            p += __shfl_xor_sync(0xffffffffu, p, 2);
            p += __shfl_xor_sync(0xffffffffu, p, 4);
            p += __shfl_xor_sync(0xffffffffu, p, 8);
            if (n == 0){
                float rv = s_res[buf][i][dloc];
                s_y[i][dloc] = fmaf(uv, Dd, p) * siluf(rv);
            }
        }
        __syncthreads();
        if (more){
            int nb = buf ^ 1;
            s_dv [nb][lt][ld] = r_dv;
            s_uv [nb][lt][ld] = r_uv;
            s_res[nb][lt][ld] = r_res;
            #pragma unroll
            for (int r = 0; r < 4; r++)
                s_bc[nb][bt + r*4][bcc] = r_bc[r];
        }
        {
            float v = s_y[lt][ld];
            __nv_bfloat16 hh, ll; split1(v, hh, ll);
            size_t o = (base + tcb + lt)*DI + dbase + ld;
            g_yh[o] = hh; g_yl[o] = ll;
        }
        __syncthreads();
        buf ^= 1;
    }
}

// ---------------- mean pool over T ----------------
__global__ void pool_kernel(){
    int b = blockIdx.x;
    int c = threadIdx.x;
    const float* p = g_hn + (size_t)b*Tsz*DM + c;
    float s0=0.f, s1=0.f, s2=0.f, s3=0.f;
    for (int t = 0; t < Tsz; t += 4){
        s0 += p[(size_t)(t+0)*DM];
        s1 += p[(size_t)(t+1)*DM];
        s2 += p[(size_t)(t+2)*DM];
        s3 += p[(size_t)(t+3)*DM];
    }
    g_pooled[b*DM + c] = (s0+s1+s2+s3) * (1.f/1024.f);
}

// ---------------- classifier head ----------------
__global__ void fine_kernel(const float* __restrict__ fw, const float* __restrict__ fb,
                            float* __restrict__ out){
    int b = blockIdx.x;
    int nn = threadIdx.x;
    if (nn >= NCLS) return;
    const float* pr = g_pooled + b*DM;
    const float* wr = fw + nn*DM;
    float s = fb[nn];
    for (int k = 0; k < DM; k++) s = fmaf(pr[k], wr[k], s);
    out[b*NCLS + nn] = s;
}

// ---------------- launch ----------------
extern "C" void kernel_launch(void* const* d_in, const int* in_sizes, int n_in,
                              void* d_out, int out_size)
{
    const float* x          = (const float*)d_in[0];
    const float* embed_w    = (const float*)d_in[1];
    const float* embed_b    = (const float*)d_in[2];
    const float* pre_g      = (const float*)d_in[3];
    const float* pre_b      = (const float*)d_in[4];
    const float* in_proj_w  = (const float*)d_in[5];
    const float* conv_w     = (const float*)d_in[6];
    const float* conv_b     = (const float*)d_in[7];
    const float* x_proj_w   = (const float*)d_in[8];
    const float* dt_proj_w  = (const float*)d_in[9];
    const float* dt_proj_b  = (const float*)d_in[10];
    const float* A_log      = (const float*)d_in[11];
    const float* Dp         = (const float*)d_in[12];
    const float* out_proj_w = (const float*)d_in[13];
    const float* post_g     = (const float*)d_in[14];
    const float* post_b     = (const float*)d_in[15];
    const float* fine_w     = (const float*)d_in[16];
    const float* fine_b     = (const float*)d_in[17];
    float* out = (float*)d_out;

    // symbol addresses
    void *p_fkh,*p_fkl,*p_feat,*p_hn,*p_hnh,*p_hnl,*p_xz,*p_xmh,*p_xml,*p_dbl,*p_dth,*p_dtl,
         *p_delta,*p_yh,*p_yl,
         *p_wembh,*p_wembl,*p_winh,*p_winl,*p_wxph,*p_wxpl,*p_wdth,*p_wdtl,*p_wouth,*p_woutl;
    cudaGetSymbolAddress(&p_fkh, g_fk_hi);   cudaGetSymbolAddress(&p_fkl, g_fk_lo);
    cudaGetSymbolAddress(&p_feat, g_feat);   cudaGetSymbolAddress(&p_hn, g_hn);
    cudaGetSymbolAddress(&p_hnh, g_hn_hi);   cudaGetSymbolAddress(&p_hnl, g_hn_lo);
    cudaGetSymbolAddress(&p_xz, g_xz);
    cudaGetSymbolAddress(&p_xmh, g_xm_hi);   cudaGetSymbolAddress(&p_xml, g_xm_lo);
    cudaGetSymbolAddress(&p_dbl, g_dbl);
    cudaGetSymbolAddress(&p_dth, g_dt_hi);   cudaGetSymbolAddress(&p_dtl, g_dt_lo);
    cudaGetSymbolAddress(&p_delta, g_delta);
    cudaGetSymbolAddress(&p_yh, g_yh);       cudaGetSymbolAddress(&p_yl, g_yl);
    cudaGetSymbolAddress(&p_wembh, g_wemb_hi); cudaGetSymbolAddress(&p_wembl, g_wemb_lo);
    cudaGetSymbolAddress(&p_winh, g_win_hi);   cudaGetSymbolAddress(&p_winl, g_win_lo);
    cudaGetSymbolAddress(&p_wxph, g_wxp_hi);   cudaGetSymbolAddress(&p_wxpl, g_wxp_lo);
    cudaGetSymbolAddress(&p_wdth, g_wdt_hi);   cudaGetSymbolAddress(&p_wdtl, g_wdt_lo);
    cudaGetSymbolAddress(&p_wouth, g_wout_hi); cudaGetSymbolAddress(&p_woutl, g_wout_lo);

    const int SM_G64 = 2 * ((256 + 128)*(64+8)) * 2;   // 110592 B
    const int SM_G16 = 2 * ((256 + 128)*(16+8)) * 2;   // 36864 B
    cudaFuncSetAttribute(gemm_bf<64,64>, cudaFuncAttributeMaxDynamicSharedMemorySize, SM_G64);
    cudaFuncSetAttribute(gemm_bf<64,16>, cudaFuncAttributeMaxDynamicSharedMemorySize, SM_G16);

    // 0) weight conversion (bf16 hi/lo, padded)
    splitw_kernel<<<(DM*KF+255)/256,   256>>>(embed_w,   (__nv_bfloat16*)p_wembh, (__nv_bfloat16*)p_wembl, DM,   225, KF,  DM*KF);
    splitw_kernel<<<(1024*DM+255)/256, 256>>>(in_proj_w, (__nv_bfloat16*)p_winh,  (__nv_bfloat16*)p_winl,  1024, DM,  DM,  1024*DM);
    splitw_kernel<<<(64*DI+255)/256,   256>>>(x_proj_w,  (__nv_bfloat16*)p_wxph,  (__nv_bfloat16*)p_wxpl,  48,   DI,  DI,  64*DI);
    splitw_kernel<<<(DI*16+255)/256,   256>>>(dt_proj_w, (__nv_bfloat16*)p_wdth,  (__nv_bfloat16*)p_wdtl,  DI,   16,  16,  DI*16);
    splitw_kernel<<<(DM*DI+255)/256,   256>>>(out_proj_w,(__nv_bfloat16*)p_wouth, (__nv_bfloat16*)p_woutl, DM,   DI,  DI,  DM*DI);

    // 1) features
    feat_kernel<<<(Msz*25 + 255)/256, 256>>>(x);

    // 2) embed GEMM: feat = featK @ embed_wp^T + embed_b
    gemm_bf<64,64><<<dim3(DM/64, Msz/128), 256, SM_G64>>>(
        KF, DM,
        (const __nv_bfloat16*)p_fkh, (const __nv_bfloat16*)p_fkl, KF,
        (const __nv_bfloat16*)p_wembh, (const __nv_bfloat16*)p_wembl, KF,
        (float*)p_feat, DM, embed_b, nullptr, 0, 0);

    // 3) pre-LN -> bf16 hi/lo
    ln_kernel<<<Msz/8, 256>>>((const float*)p_feat, pre_g, pre_b,
        nullptr, (__nv_bfloat16*)p_hnh, (__nv_bfloat16*)p_hnl, 1);

    // 4) in_proj GEMM: xz = hn @ in_proj_w^T
    gemm_bf<64,64><<<dim3(1024/64, Msz/128), 256, SM_G64>>>(
        DM, 1024,
        (const __nv_bfloat16*)p_hnh, (const __nv_bfloat16*)p_hnl, DM,
        (const __nv_bfloat16*)p_winh, (const __nv_bfloat16*)p_winl, DM,
        (float*)p_xz, 1024, nullptr, nullptr, 0, 0);

    // 5) depthwise conv + silu
    conv_silu_kernel<<<(Msz*DI)/256, 256>>>(conv_w, conv_b);

    // 6) x_proj GEMM: dbl = xmc @ x_proj_w^T  (N=48)
    gemm_bf<64,64><<<dim3(1, Msz/128), 256, SM_G64>>>(
        DI, 48,
        (const __nv_bfloat16*)p_xmh, (const __nv_bfloat16*)p_xml, DI,
        (const __nv_bfloat16*)p_wxph, (const __nv_bfloat16*)p_wxpl, DI,
        (float*)p_dbl, 48, nullptr, nullptr, 0, 0);

    // 6b) split dt columns
    split_dt_kernel<<<(Msz*16)/256, 256>>>();

    // 7) dt_proj GEMM + softplus
    gemm_bf<64,16><<<dim3(DI/64, Msz/128), 256, SM_G16>>>(
        16, DI,
        (const __nv_bfloat16*)p_dth, (const __nv_bfloat16*)p_dtl, 16,
        (const __nv_bfloat16*)p_wdth, (const __nv_bfloat16*)p_wdtl, 16,
        (float*)p_delta, DI, dt_proj_b, nullptr, 0, 1);

    // 8) selective scan (gate fused, bf16 hi/lo y out)
    scan_kernel<<<Bsz*64, 128>>>(A_log, Dp);

    // 9) out_proj GEMM + residual
    gemm_bf<64,64><<<dim3(DM/64, Msz/128), 256, SM_G64>>>(
        DI, DM,
        (const __nv_bfloat16*)p_yh, (const __nv_bfloat16*)p_yl, DI,
        (const __nv_bfloat16*)p_wouth, (const __nv_bfloat16*)p_woutl, DI,
        (float*)p_feat, DM, nullptr, (const float*)p_feat, DM, 0);

    // 10) post-LN -> fp32
    ln_kernel<<<Msz/8, 256>>>((const float*)p_feat, post_g, post_b,
        (float*)p_hn, nullptr, nullptr, 0);

    // 11) mean pool
    pool_kernel<<<Bsz, 256>>>();

    // 12) classifier
    fine_kernel<<<Bsz, 64>>>(fine_w, fine_b, out);

    (void)in_sizes; (void)n_in; (void)out_size;
}

// round 7
// speedup vs baseline: 2.1465x; 1.1591x over previous
#include <cuda_runtime.h>
#include <cuda_fp16.h>
#include <cstdint>

// ---------------- problem constants ----------------
#define Bsz 8
#define Tsz 1024
#define Msz (Bsz*Tsz)        // 8192
#define DM  256
#define DI  512
#define DS  16
#define NCLS 60
#define KF  256              // 225 padded to 256 (zero-filled)
#define CH  16               // scan chunk

// ---------------- device scratch ----------------
__device__ __half g_fk_h[Msz*KF];          // features fp16 (A of embed)
__device__ float  g_feat[Msz*DM];
__device__ float  g_hn[Msz*DM];
__device__ __half g_hn_h[Msz*DM];          // A of in_proj
__device__ float  g_xz[(size_t)Msz*1024];
__device__ float  g_xmc[Msz*DI];
__device__ __half g_xm_h[Msz*DI];          // A of x_proj
__device__ float  g_dbl[Msz*48];
__device__ __half g_dt_h[Msz*16];          // A of dt_proj
__device__ float  g_delta[Msz*DI];
__device__ __half g_y_h[Msz*DI];           // A of out_proj
__device__ float  g_pooled[Bsz*DM];
// weights fp16 hi/lo (padded)
__device__ __half g_wemb_h[DM*KF],  g_wemb_l[DM*KF];     // 256 x 256
__device__ __half g_win_h[1024*DM], g_win_l[1024*DM];    // 1024 x 256
__device__ __half g_wxp_h[64*DI],   g_wxp_l[64*DI];      // 48->64 x 512
__device__ __half g_wdt_h[DI*16],   g_wdt_l[DI*16];      // 512 x 16
__device__ __half g_wout_h[DM*DI],  g_wout_l[DM*DI];     // 256 x 512

__device__ __forceinline__ float softplusf(float v){
    return v > 20.f ? v : log1pf(expf(v));
}
__device__ __forceinline__ float siluf(float v){
    return v / (1.f + __expf(-v));
}
__device__ __forceinline__ void splith(float v, __half& h, __half& l){
    h = __float2half_rn(v);
    l = __float2half_rn(v - __half2float(h));
}
__device__ __forceinline__ uint32_t smem_u32(const void* p){
    uint32_t a;
    asm("{ .reg .u64 t; cvta.to.shared.u64 t, %1; cvt.u32.u64 %0, t; }" : "=r"(a) : "l"(p));
    return a;
}
__device__ __forceinline__ void cp16(uint32_t dst, const void* src){
    asm volatile("cp.async.cg.shared.global [%0], [%1], 16;" :: "r"(dst), "l"(src));
}
__device__ __forceinline__ void mma16816(float* d, const uint32_t* a, const uint32_t* b){
    asm volatile(
        "mma.sync.aligned.m16n8k16.row.col.f32.f16.f16.f32 "
        "{%0,%1,%2,%3}, {%4,%5,%6,%7}, {%8,%9}, {%0,%1,%2,%3};"
        : "+f"(d[0]), "+f"(d[1]), "+f"(d[2]), "+f"(d[3])
        : "r"(a[0]), "r"(a[1]), "r"(a[2]), "r"(a[3]), "r"(b[0]), "r"(b[1]));
}
__device__ __forceinline__ void ldsm4(uint32_t* r, uint32_t addr){
    asm volatile("ldmatrix.sync.aligned.m8n8.x4.shared.b16 {%0,%1,%2,%3}, [%4];"
        : "=r"(r[0]), "=r"(r[1]), "=r"(r[2]), "=r"(r[3]) : "r"(addr));
}
__device__ __forceinline__ void ldsm2(uint32_t* r, uint32_t addr){
    asm volatile("ldmatrix.sync.aligned.m8n8.x2.shared.b16 {%0,%1}, [%2];"
        : "=r"(r[0]), "=r"(r[1]) : "r"(addr));
}

// ---------------- merged prep: all weight splits + feature construction ----------------
// grid = 2752 blocks x 256 thr
__global__ void prep_kernel(const float* __restrict__ x,
                            const float* __restrict__ embed_w,
                            const float* __restrict__ in_proj_w,
                            const float* __restrict__ x_proj_w,
                            const float* __restrict__ dt_proj_w,
                            const float* __restrict__ out_proj_w){
    const int b = blockIdx.x;
    const int t = threadIdx.x;
    if (b < 256){                               // embed_w: 256 x 225 -> 256 x 256 hi/lo
        int i = b*256 + t;
        int n = i >> 8, k = i & 255;
        float v = (k < 225) ? embed_w[n*225 + k] : 0.f;
        __half h, l; splith(v, h, l);
        g_wemb_h[i] = h; g_wemb_l[i] = l;
    } else if (b < 1280){                       // in_proj_w: 1024 x 256
        int i = (b-256)*256 + t;
        __half h, l; splith(in_proj_w[i], h, l);
        g_win_h[i] = h; g_win_l[i] = l;
    } else if (b < 1408){                       // x_proj_w: 48 x 512 -> 64 x 512
        int i = (b-1280)*256 + t;
        int n = i >> 9;
        float v = (n < 48) ? x_proj_w[i] : 0.f;
        __half h, l; splith(v, h, l);
        g_wxp_h[i] = h; g_wxp_l[i] = l;
    } else if (b < 1440){                       // dt_proj_w: 512 x 16
        int i = (b-1408)*256 + t;
        __half h, l; splith(dt_proj_w[i], h, l);
        g_wdt_h[i] = h; g_wdt_l[i] = l;
    } else if (b < 1952){                       // out_proj_w: 256 x 512
        int i = (b-1440)*256 + t;
        __half h, l; splith(out_proj_w[i], h, l);
        g_wout_h[i] = h; g_wout_l[i] = l;
    } else {                                    // features: Msz*25 items
        int i = (b-1952)*256 + t;
        if (i >= Msz*25) return;
        int j = i % 25;
        int m = i / 25;
        int tt = m & (Tsz-1);
        const float* xr  = x + (size_t)m*75;
        const float* xr1 = xr - 75;
        const float* xr2 = xr - 150;
        size_t ob = (size_t)m*KF + j*9;
        #pragma unroll
        for (int c = 0; c < 3; c++){
            float p0 = xr[j*3+c]  - xr[c];
            float p1 = (tt>=1) ? (xr1[j*3+c] - xr1[c]) : 0.f;
            float p2 = (tt>=2) ? (xr2[j*3+c] - xr2[c]) : 0.f;
            float vel   = (tt>=1) ? (p0 - p1) : 0.f;
            float velm1 = (tt>=2) ? (p1 - p2) : 0.f;
            float acc   = (tt>=1) ? (vel - velm1) : 0.f;
            g_fk_h[ob+c]   = __float2half_rn(p0);
            g_fk_h[ob+3+c] = __float2half_rn(vel);
            g_fk_h[ob+6+c] = __float2half_rn(acc);
        }
        if (j == 0){
            __half z = __float2half_rn(0.f);
            for (int k = 225; k < KF; k++) g_fk_h[(size_t)m*KF + k] = z;
        }
    }
}

// dbl[:, :16] -> dt fp16
__global__ void split_dt_kernel(){
    int i = blockIdx.x*256 + threadIdx.x;   // over Msz*16
    int row = i >> 4, k = i & 15;
    g_dt_h[i] = __float2half_rn(g_dbl[(size_t)row*48 + k]);
}

// ---------------- fp16 2-pass tensor-core GEMM (NT): C = A @ W^T ----------------
// A: fp16 [M x K]; W hi/lo: fp16 [Npad x K]. acc += A*Wh + A*Wl (fp32 regs).
// cp.async double-buffered, block 256 thr, tile 128 x NT.
template<int NT, int KC>
__global__ __launch_bounds__(256) void gemm_h(
    int K, int N,
    const __half* __restrict__ A_, int lda,
    const __half* __restrict__ Wh_, const __half* __restrict__ Wl_, int ldw,
    float* __restrict__ C, int ldc,
    const float* __restrict__ bias,
    const float* __restrict__ addC, int ldadd,
    int act)
{
    extern __shared__ char smem[];
    constexpr int LDT = KC + 8;                   // fp16 elems per padded row
    constexpr int SBUF = (128 + 2*NT)*LDT;        // elems per buffer
    constexpr int C8 = KC/8;                      // 16B chunks per row
    constexpr int NWT = NT/32;
    const uint32_t sb = smem_u32(smem);
    const int tid = threadIdx.x, lane = tid & 31, warp = tid >> 5;
    const int bm = blockIdx.y * 128;
    const int bn = blockIdx.x * NT;
    const int nv = min(NT, N - bn);
    const int wm = (warp & 1) * 64;
    const int wn = (warp >> 1) * (NT/4);

    float acc[4][NWT][4];
    #pragma unroll
    for (int mt = 0; mt < 4; mt++)
        #pragma unroll
        for (int nt = 0; nt < NWT; nt++)
            #pragma unroll
            for (int i = 0; i < 4; i++) acc[mt][nt][i] = 0.f;

    const int a_row = wm + (lane & 15);
    const int a_colb = (lane >> 4) * 8;
    const int b_row = wn + (lane & 7);
    const int b_colb = ((lane >> 3) & 1) * 8;

    const int NC = K / KC;

    auto load_chunk = [&](int c, int bf){
        uint32_t base = sb + (uint32_t)(bf * SBUF * 2);
        const size_t koff = (size_t)c * KC;
        #pragma unroll 2
        for (int idx = tid; idx < 128*C8; idx += 256){
            int row = idx / C8, c8 = idx - row*C8;
            cp16(base + (uint32_t)((row*LDT + c8*8) * 2),
                 A_ + (size_t)(bm + row)*lda + koff + c8*8);
        }
        #pragma unroll 2
        for (int idx = tid; idx < NT*C8; idx += 256){
            int row = idx / C8, c8 = idx - row*C8;
            uint32_t d = base + (uint32_t)(((128 + row)*LDT + c8*8) * 2);
            size_t s = (size_t)(bn + row)*ldw + koff + c8*8;
            cp16(d,              Wh_ + s);
            cp16(d + NT*LDT*2,   Wl_ + s);
        }
    };

    int buf = 0;
    load_chunk(0, 0);
    asm volatile("cp.async.commit_group;" ::: "memory");
    for (int c = 0; c < NC; c++){
        if (c + 1 < NC) load_chunk(c + 1, buf ^ 1);
        asm volatile("cp.async.commit_group;" ::: "memory");
        if (c + 1 < NC) asm volatile("cp.async.wait_group 1;" ::: "memory");
        else            asm volatile("cp.async.wait_group 0;" ::: "memory");
        __syncthreads();

        uint32_t abase = sb + (uint32_t)(buf * SBUF * 2);
        #pragma unroll
        for (int kk = 0; kk < KC; kk += 16){
            uint32_t a[4][4];
            #pragma unroll
            for (int mt = 0; mt < 4; mt++)
                ldsm4(a[mt], abase + (uint32_t)(((a_row + mt*16)*LDT + kk + a_colb) * 2));
            uint32_t bh[NWT][2], bl[NWT][2];
            #pragma unroll
            for (int nt = 0; nt < NWT; nt++){
                uint32_t bd = abase + (uint32_t)(((128 + b_row + nt*8)*LDT + kk + b_colb) * 2);
                ldsm2(bh[nt], bd);
                ldsm2(bl[nt], bd + NT*LDT*2);
            }
            #pragma unroll
            for (int mt = 0; mt < 4; mt++)
                #pragma unroll
                for (int nt = 0; nt < NWT; nt++){
                    mma16816(acc[mt][nt], a[mt], bh[nt]);
                    mma16816(acc[mt][nt], a[mt], bl[nt]);
                }
        }
        __syncthreads();
        buf ^= 1;
    }

    // epilogue: fragment -> global, fused bias / softplus / residual
    #pragma unroll
    for (int mt = 0; mt < 4; mt++){
        #pragma unroll
        for (int i = 0; i < 4; i++){
            int m = bm + wm + mt*16 + (lane >> 2) + (i >> 1)*8;
            #pragma unroll
            for (int nt = 0; nt < NWT; nt++){
                int n = wn + nt*8 + (lane & 3)*2 + (i & 1);
                if (n < nv){
                    int gn = bn + n;
                    float v = acc[mt][nt][i];
                    if (bias) v += bias[gn];
                    if (act)  v  = softplusf(v);
                    if (addC) v += addC[(size_t)m*ldadd + gn];
                    C[(size_t)m*ldc + gn] = v;
                }
            }
        }
    }
}

// ---------------- layernorm, warp-per-row (256 cols) ----------------
// mode 0: fp32 out ; mode 1: fp16 out
__global__ __launch_bounds__(256) void ln_kernel(
    const float* __restrict__ in, const float* __restrict__ g,
    const float* __restrict__ bta, float* __restrict__ outf,
    __half* __restrict__ oh, int mode)
{
    int row  = blockIdx.x*8 + (threadIdx.x >> 5);
    int lane = threadIdx.x & 31;
    const float* p = in + (size_t)row*DM + lane*8;
    float4 v0 = *(const float4*)p;
    float4 v1 = *(const float4*)(p + 4);
    float va[8] = {v0.x,v0.y,v0.z,v0.w,v1.x,v1.y,v1.z,v1.w};
    float s = 0.f, q = 0.f;
    #pragma unroll
    for (int i = 0; i < 8; i++){ s += va[i]; q = fmaf(va[i], va[i], q); }
    #pragma unroll
    for (int o = 16; o; o >>= 1){
        s += __shfl_xor_sync(0xffffffffu, s, o);
        q += __shfl_xor_sync(0xffffffffu, q, o);
    }
    float mu  = s * (1.f/256.f);
    float var = q * (1.f/256.f) - mu*mu;
    float inv = rsqrtf(var + 1e-5f);
    float4 g0 = *(const float4*)(g + lane*8);
    float4 g1 = *(const float4*)(g + lane*8 + 4);
    float4 b0 = *(const float4*)(bta + lane*8);
    float4 b1 = *(const float4*)(bta + lane*8 + 4);
    float ga[8] = {g0.x,g0.y,g0.z,g0.w,g1.x,g1.y,g1.z,g1.w};
    float ba[8] = {b0.x,b0.y,b0.z,b0.w,b1.x,b1.y,b1.z,b1.w};
    float r[8];
    #pragma unroll
    for (int i = 0; i < 8; i++) r[i] = (va[i] - mu) * inv * ga[i] + ba[i];
    if (mode == 0){
        float* o = outf + (size_t)row*DM + lane*8;
        *(float4*)o       = make_float4(r[0], r[1], r[2], r[3]);
        *(float4*)(o + 4) = make_float4(r[4], r[5], r[6], r[7]);
    } else {
        size_t ob = (size_t)row*DM + lane*8;
        #pragma unroll
        for (int i = 0; i < 8; i++) oh[ob + i] = __float2half_rn(r[i]);
    }
}

// ---------------- causal depthwise conv (k=4) + silu (fp32 + fp16 out) ----------------
__global__ void conv_silu_kernel(const float* __restrict__ cw, const float* __restrict__ cb){
    int i = blockIdx.x*blockDim.x + threadIdx.x;
    int d = i & (DI-1);
    int m = i >> 9;
    int t = m & (Tsz-1);
    float w0 = cw[d*4+0], w1 = cw[d*4+1], w2 = cw[d*4+2], w3 = cw[d*4+3];
    float a = cb[d];
    a = fmaf(w3, g_xz[(size_t)m*1024 + d], a);
    if (t >= 1) a = fmaf(w2, g_xz[(size_t)(m-1)*1024 + d], a);
    if (t >= 2) a = fmaf(w1, g_xz[(size_t)(m-2)*1024 + d], a);
    if (t >= 3) a = fmaf(w0, g_xz[(size_t)(m-3)*1024 + d], a);
    float sv = siluf(a);
    g_xmc[i] = sv;
    g_xm_h[i] = __float2half_rn(sv);
}

// ---------------- selective scan: 512 blocks x 128 thr, 8 channels/block, gate fused ----------------
__global__ __launch_bounds__(128) void scan_kernel(
    const float* __restrict__ A_log, const float* __restrict__ Dp)
{
    __shared__ float s_dv [2][CH][8];
    __shared__ float s_uv [2][CH][8];
    __shared__ float s_res[2][CH][8];
    __shared__ float s_bc [2][CH][32];
    __shared__ float s_y  [CH][8];

    const int tid  = threadIdx.x;
    const int lane = tid & 31;
    const int warp = tid >> 5;
    const int b     = blockIdx.x >> 6;
    const int dbase = (blockIdx.x & 63) * 8;
    const int dloc  = warp*2 + (lane >> 4);
    const int d     = dbase + dloc;
    const int n     = lane & 15;

    const float a  = -expf(A_log[d*DS + n]);
    const float Dd = Dp[d];
    const size_t base = (size_t)b * Tsz;

    const int lt = tid >> 3;      // 0..15
    const int ld = tid & 7;       // 0..7
    const int bt = tid >> 5;      // 0..3
    const int bcc = tid & 31;

    {
        size_t row = base + lt;
        s_dv [0][lt][ld] = g_delta[row*DI + dbase + ld];
        s_uv [0][lt][ld] = g_xmc [row*DI + dbase + ld];
        s_res[0][lt][ld] = g_xz  [row*1024 + 512 + dbase + ld];
        #pragma unroll
        for (int r = 0; r < 4; r++)
            s_bc[0][bt + r*4][bcc] = g_dbl[(base + bt + r*4)*48 + 16 + bcc];
    }
    __syncthreads();

    float h = 0.f;
    int buf = 0;
    for (int tcb = 0; tcb < Tsz; tcb += CH){
        const bool more = (tcb + CH) < Tsz;
        float r_dv=0.f, r_uv=0.f, r_res=0.f, r_bc[4]={0.f,0.f,0.f,0.f};
        if (more){
            size_t row = base + tcb + CH + lt;
            r_dv  = g_delta[row*DI + dbase + ld];
            r_uv  = g_xmc [row*DI + dbase + ld];
            r_res = g_xz  [row*1024 + 512 + dbase + ld];
            #pragma unroll
            for (int r = 0; r < 4; r++)
                r_bc[r] = g_dbl[(base + tcb + CH + bt + r*4)*48 + 16 + bcc];
        }
        #pragma unroll
        for (int i = 0; i < CH; i++){
            float dv = s_dv[buf][i][dloc];
            float uv = s_uv[buf][i][dloc];
            float Bn = s_bc[buf][i][n];
            float Cn = s_bc[buf][i][16 + n];
            float dA = __expf(dv * a);
            h = fmaf(dA, h, dv * Bn * uv);
            float p = h * Cn;
            p += __shfl_xor_sync(0xffffffffu, p, 1);
            p += __shfl_xor_sync(0xffffffffu, p, 2);
            p += __shfl_xor_sync(0xffffffffu, p, 4);
            p += __shfl_xor_sync(0xffffffffu, p, 8);
            if (n == 0){
                float rv = s_res[buf][i][dloc];
                s_y[i][dloc] = fmaf(uv, Dd, p) * siluf(rv);
            }
        }
        __syncthreads();
        if (more){
            int nb = buf ^ 1;
            s_dv [nb][lt][ld] = r_dv;
            s_uv [nb][lt][ld] = r_uv;
            s_res[nb][lt][ld] = r_res;
            #pragma unroll
            for (int r = 0; r < 4; r++)
                s_bc[nb][bt + r*4][bcc] = r_bc[r];
        }
        g_y_h[(base + tcb + lt)*DI + dbase + ld] = __float2half_rn(s_y[lt][ld]);
        __syncthreads();
        buf ^= 1;
    }
}

// ---------------- mean pool over T ----------------
__global__ void pool_kernel(){
    int b = blockIdx.x;
    int c = threadIdx.x;
    const float* p = g_hn + (size_t)b*Tsz*DM + c;
    float s0=0.f, s1=0.f, s2=0.f, s3=0.f;
    for (int t = 0; t < Tsz; t += 4){
        s0 += p[(size_t)(t+0)*DM];
        s1 += p[(size_t)(t+1)*DM];
        s2 += p[(size_t)(t+2)*DM];
        s3 += p[(size_t)(t+3)*DM];
    }
    g_pooled[b*DM + c] = (s0+s1+s2+s3) * (1.f/1024.f);
}

// ---------------- classifier head ----------------
__global__ void fine_kernel(const float* __restrict__ fw, const float* __restrict__ fb,
                            float* __restrict__ out){
    int b = blockIdx.x;
    int nn = threadIdx.x;
    if (nn >= NCLS) return;
    const float* pr = g_pooled + b*DM;
    const float* wr = fw + nn*DM;
    float s = fb[nn];
    for (int k = 0; k < DM; k++) s = fmaf(pr[k], wr[k], s);
    out[b*NCLS + nn] = s;
}

// ---------------- launch ----------------
extern "C" void kernel_launch(void* const* d_in, const int* in_sizes, int n_in,
                              void* d_out, int out_size)
{
    const float* x          = (const float*)d_in[0];
    const float* embed_w    = (const float*)d_in[1];
    const float* embed_b    = (const float*)d_in[2];
    const float* pre_g      = (const float*)d_in[3];
    const float* pre_b      = (const float*)d_in[4];
    const float* in_proj_w  = (const float*)d_in[5];
    const float* conv_w     = (const float*)d_in[6];
    const float* conv_b     = (const float*)d_in[7];
    const float* x_proj_w   = (const float*)d_in[8];
    const float* dt_proj_w  = (const float*)d_in[9];
    const float* dt_proj_b  = (const float*)d_in[10];
    const float* A_log      = (const float*)d_in[11];
    const float* Dp         = (const float*)d_in[12];
    const float* out_proj_w = (const float*)d_in[13];
    const float* post_g     = (const float*)d_in[14];
    const float* post_b     = (const float*)d_in[15];
    const float* fine_w     = (const float*)d_in[16];
    const float* fine_b     = (const float*)d_in[17];
    float* out = (float*)d_out;

    void *p_fk,*p_feat,*p_hn,*p_hnh,*p_xz,*p_xmh,*p_dbl,*p_dth,*p_delta,*p_yh,
         *p_wembh,*p_wembl,*p_winh,*p_winl,*p_wxph,*p_wxpl,*p_wdth,*p_wdtl,*p_wouth,*p_woutl;
    cudaGetSymbolAddress(&p_fk, g_fk_h);
    cudaGetSymbolAddress(&p_feat, g_feat);   cudaGetSymbolAddress(&p_hn, g_hn);
    cudaGetSymbolAddress(&p_hnh, g_hn_h);
    cudaGetSymbolAddress(&p_xz, g_xz);       cudaGetSymbolAddress(&p_xmh, g_xm_h);
    cudaGetSymbolAddress(&p_dbl, g_dbl);     cudaGetSymbolAddress(&p_dth, g_dt_h);
    cudaGetSymbolAddress(&p_delta, g_delta); cudaGetSymbolAddress(&p_yh, g_y_h);
    cudaGetSymbolAddress(&p_wembh, g_wemb_h); cudaGetSymbolAddress(&p_wembl, g_wemb_l);
    cudaGetSymbolAddress(&p_winh, g_win_h);   cudaGetSymbolAddress(&p_winl, g_win_l);
    cudaGetSymbolAddress(&p_wxph, g_wxp_h);   cudaGetSymbolAddress(&p_wxpl, g_wxp_l);
    cudaGetSymbolAddress(&p_wdth, g_wdt_h);   cudaGetSymbolAddress(&p_wdtl, g_wdt_l);
    cudaGetSymbolAddress(&p_wouth, g_wout_h); cudaGetSymbolAddress(&p_woutl, g_wout_l);

    const int SM_G64 = 2 * ((128 + 128)*(64+8)) * 2;   // 73728 B
    const int SM_G16 = 2 * ((128 + 128)*(16+8)) * 2;   // 24576 B
    cudaFuncSetAttribute(gemm_h<64,64>, cudaFuncAttributeMaxDynamicSharedMemorySize, SM_G64);
    cudaFuncSetAttribute(gemm_h<64,16>, cudaFuncAttributeMaxDynamicSharedMemorySize, SM_G16);

    // 1) merged prep (weight splits + features)
    prep_kernel<<<2752, 256>>>(x, embed_w, in_proj_w, x_proj_w, dt_proj_w, out_proj_w);

    // 2) embed GEMM: feat = featK @ embed_w^T + embed_b
    gemm_h<64,64><<<dim3(DM/64, Msz/128), 256, SM_G64>>>(
        KF, DM,
        (const __half*)p_fk, KF,
        (const __half*)p_wembh, (const __half*)p_wembl, KF,
        (float*)p_feat, DM, embed_b, nullptr, 0, 0);

    // 3) pre-LN -> fp16
    ln_kernel<<<Msz/8, 256>>>((const float*)p_feat, pre_g, pre_b,
        nullptr, (__half*)p_hnh, 1);

    // 4) in_proj GEMM (4th launch -> ncu profile target)
    gemm_h<64,64><<<dim3(1024/64, Msz/128), 256, SM_G64>>>(
        DM, 1024,
        (const __half*)p_hnh, DM,
        (const __half*)p_winh, (const __half*)p_winl, DM,
        (float*)p_xz, 1024, nullptr, nullptr, 0, 0);

    // 5) depthwise conv + silu
    conv_silu_kernel<<<(Msz*DI)/256, 256>>>(conv_w, conv_b);

    // 6) x_proj GEMM: dbl = xmc @ x_proj_w^T  (N=48)
    gemm_h<64,64><<<dim3(1, Msz/128), 256, SM_G64>>>(
        DI, 48,
        (const __half*)p_xmh, DI,
        (const __half*)p_wxph, (const __half*)p_wxpl, DI,
        (float*)p_dbl, 48, nullptr, nullptr, 0, 0);

    // 7) split dt columns
    split_dt_kernel<<<(Msz*16)/256, 256>>>();

    // 8) dt_proj GEMM + softplus
    gemm_h<64,16><<<dim3(DI/64, Msz/128), 256, SM_G16>>>(
        16, DI,
        (const __half*)p_dth, 16,
        (const __half*)p_wdth, (const __half*)p_wdtl, 16,
        (float*)p_delta, DI, dt_proj_b, nullptr, 0, 1);

    // 9) selective scan (gate fused, fp16 y out)
    scan_kernel<<<Bsz*64, 128>>>(A_log, Dp);

    // 10) out_proj GEMM + residual
    gemm_h<64,64><<<dim3(DM/64, Msz/128), 256, SM_G64>>>(
        DI, DM,
        (const __half*)p_yh, DI,
        (const __half*)p_wouth, (const __half*)p_woutl, DI,
        (float*)p_feat, DM, nullptr, (const float*)p_feat, DM, 0);

    // 11) post-LN -> fp32
    ln_kernel<<<Msz/8, 256>>>((const float*)p_feat, post_g, post_b,
        (float*)p_hn, nullptr, 0);

    // 12) mean pool
    pool_kernel<<<Bsz, 256>>>();

    // 13) classifier
    fine_kernel<<<Bsz, 64>>>(fine_w, fine_b, out);

    (void)in_sizes; (void)n_in; (void)out_size;
}